// round 11
// baseline (speedup 1.0000x reference)
#include <cuda_runtime.h>
#include <cstring>
#include <math.h>

static __device__ float g_xs[512 * 7500];
static __device__ float g_h1[512 * 42336];
static __device__ float g_h2[512 * 9344];
static __device__ float g_ypart[16 * 512 * 64];
static __device__ float g_y[512 * 64];
static __device__ float g_x[512 * 301 * 64];
static __device__ float g_qkv[512 * 301 * 192];   // token-major [b][301][192]
static __device__ float g_o[512 * 301 * 64];

__device__ __forceinline__ float2 ffma2(float2 a, float2 b, float2 c) {
    unsigned long long ua, ub, uc, ud;
    memcpy(&ua, &a, 8); memcpy(&ub, &b, 8); memcpy(&uc, &c, 8);
    asm("fma.rn.f32x2 %0, %1, %2, %3;" : "=l"(ud) : "l"(ua), "l"(ub), "l"(uc));
    float2 d; memcpy(&d, &ud, 8);
    return d;
}

// K1: SSE gate
__global__ void k_sse(const float* __restrict__ in, const float* __restrict__ sw,
                      const float* __restrict__ sb) {
    int b = blockIdx.x, tid = threadIdx.x;
    __shared__ float s_w[300], s_g[25];
    const float* x = in + b * 7500;
    for (int i = tid; i < 300; i += 256) s_w[i] = sw[i];
    __syncthreads();
    int warp = tid >> 5, lane = tid & 31;
    for (int p = warp; p < 25; p += 8) {
        float acc = 0.f;
        const float* xp = x + p * 300;
        for (int c = lane; c < 300; c += 32) acc += xp[c] * s_w[c];
        #pragma unroll
        for (int o = 16; o; o >>= 1) acc += __shfl_xor_sync(0xffffffffu, acc, o);
        if (lane == 0) s_g[p] = 1.f / (1.f + expf(-(acc + sb[0])));
    }
    __syncthreads();
    float* xo = g_xs + b * 7500;
    for (int i = tid; i < 7500; i += 256) xo[i] = x[i] * s_g[i / 300];
}

// K2: conv1 (1->16, 3x3x7) + relu
__global__ void k_conv1(const float* __restrict__ W, const float* __restrict__ B) {
    int b = blockIdx.x, tid = threadIdx.x;
    __shared__ float sx[7552], sw[1008], sb[16];
    const float* xs = g_xs + b * 7500;
    for (int i = tid; i < 7552; i += 256) sx[i] = (i < 7500) ? xs[i] : 0.f;
    for (int i = tid; i < 1008; i += 256) sw[i] = W[i];
    if (tid < 16) sb[tid] = B[tid];
    __syncthreads();
    float* out = g_h1 + b * 42336;
    int warp = tid >> 5, lane = tid & 31, w0 = lane * 10;
    for (int row = warp; row < 144; row += 8) {
        int o = row / 9, dh = row % 9, d = dh / 3, hh = dh % 3;
        const float* wp = sw + o * 63;
        float acc[10];
        #pragma unroll
        for (int u = 0; u < 10; u++) acc[u] = sb[o];
        #pragma unroll
        for (int kd = 0; kd < 3; kd++)
        #pragma unroll
        for (int kh = 0; kh < 3; kh++) {
            const float* ip = sx + (d + kd) * 1500 + (hh + kh) * 300 + w0;
            float iv[16];
            #pragma unroll
            for (int u = 0; u < 16; u++) iv[u] = ip[u];
            const float* wq = wp + kd * 21 + kh * 7;
            #pragma unroll
            for (int kw = 0; kw < 7; kw++) {
                float wv = wq[kw];
                #pragma unroll
                for (int u = 0; u < 10; u++) acc[u] += iv[u + kw] * wv;
            }
        }
        #pragma unroll
        for (int u = 0; u < 10; u++)
            if (w0 + u < 294) out[row * 294 + w0 + u] = fmaxf(acc[u], 0.f);
    }
}

// K3: conv2 (16->32, 3x3x3) + relu
__global__ void k_conv2(const float* __restrict__ W, const float* __restrict__ B) {
    extern __shared__ float sm[];
    float* s_in = sm;            // 42336
    float* s_w  = sm + 42336;    // 16*433
    int b = blockIdx.x, tid = threadIdx.x;
    const float* hin = g_h1 + b * 42336;
    for (int i = tid; i < 42336; i += 256) s_in[i] = hin[i];
    float* out = g_h2 + b * 9344;
    for (int ocg = 0; ocg < 2; ocg++) {
        __syncthreads();
        for (int i = tid; i < 6912; i += 256)
            s_w[(i / 432) * 433 + (i % 432)] = W[ocg * 6912 + i];
        __syncthreads();
        for (int t = tid; t < 1168; t += 256) {
            int oc = t & 15, w0 = (t >> 4) * 4;
            const float* wp = s_w + oc * 433;
            float a0 = 0.f, a1 = 0.f, a2 = 0.f, a3 = 0.f;
            for (int ic = 0; ic < 16; ic++)
            #pragma unroll
            for (int kd = 0; kd < 3; kd++)
            #pragma unroll
            for (int kh = 0; kh < 3; kh++) {
                const float* ip = s_in + ((ic * 3 + kd) * 3 + kh) * 294 + w0;
                float i0 = ip[0], i1 = ip[1], i2 = ip[2];
                float i3 = ip[3], i4 = ip[4], i5 = ip[5];
                const float* wq = wp + (ic * 9 + kd * 3 + kh) * 3;
                float v0 = wq[0], v1 = wq[1], v2 = wq[2];
                a0 += i0 * v0 + i1 * v1 + i2 * v2;
                a1 += i1 * v0 + i2 * v1 + i3 * v2;
                a2 += i2 * v0 + i3 * v1 + i4 * v2;
                a3 += i3 * v0 + i4 * v1 + i5 * v2;
            }
            int oco = ocg * 16 + oc;
            float bb = B[oco];
            out[oco * 292 + w0 + 0] = fmaxf(a0 + bb, 0.f);
            out[oco * 292 + w0 + 1] = fmaxf(a1 + bb, 0.f);
            out[oco * 292 + w0 + 2] = fmaxf(a2 + bb, 0.f);
            out[oco * 292 + w0 + 3] = fmaxf(a3 + bb, 0.f);
        }
    }
}

// K4: dense1 (9344->64), split-K 16
__global__ void k_dense1(const float* __restrict__ W) {
    __shared__ float sA[16][33], sB[64][33];
    int rb = blockIdx.x * 16, kc = blockIdx.y * 584, tid = threadIdx.x;
    int r = tid & 15, cg = tid >> 4;
    float a0 = 0.f, a1 = 0.f, a2 = 0.f, a3 = 0.f;
    for (int k0 = 0; k0 < 584; k0 += 32) {
        int kw = 584 - k0 < 32 ? 584 - k0 : 32;
        for (int i = tid; i < 512; i += 256) {
            int col = i & 31;
            sA[i >> 5][col] = (col < kw) ? g_h2[(rb + (i >> 5)) * 9344 + kc + k0 + col] : 0.f;
        }
        for (int i = tid; i < 2048; i += 256) {
            int col = i & 31;
            sB[i >> 5][col] = (col < kw) ? W[(i >> 5) * 9344 + kc + k0 + col] : 0.f;
        }
        __syncthreads();
        #pragma unroll
        for (int kk = 0; kk < 32; kk++) {
            float a = sA[r][kk];
            a0 += a * sB[cg * 4 + 0][kk];
            a1 += a * sB[cg * 4 + 1][kk];
            a2 += a * sB[cg * 4 + 2][kk];
            a3 += a * sB[cg * 4 + 3][kk];
        }
        __syncthreads();
    }
    float* yp = g_ypart + blockIdx.y * 32768 + (rb + r) * 64 + cg * 4;
    yp[0] = a0; yp[1] = a1; yp[2] = a2; yp[3] = a3;
}

__global__ void k_yred(const float* __restrict__ bias) {
    int i = blockIdx.x * 256 + threadIdx.x;
    float acc = bias[i & 63];
    #pragma unroll
    for (int s = 0; s < 16; s++) acc += g_ypart[s * 32768 + i];
    g_y[i] = acc;
}

// K5: patch embed + cls + pos
__global__ void k_patch(const float* __restrict__ pw, const float* __restrict__ pb,
                        const float* __restrict__ cls, const float* __restrict__ pos) {
    __shared__ float s_x[7500], s_w[1600];
    int b = blockIdx.x, tid = threadIdx.x;
    const float* xs = g_xs + b * 7500;
    for (int i = tid; i < 7500; i += 256) s_x[i] = xs[i];
    for (int i = tid; i < 1600; i += 256) s_w[i] = pw[i];
    __syncthreads();
    float* xo = g_x + b * 301 * 64;
    if (tid < 64) xo[tid] = cls[tid] + pos[tid];
    for (int idx = tid; idx < 19200; idx += 256) {
        int t = idx >> 6, o = idx & 63;
        const float* xr = s_x + t * 25;
        const float* wr = s_w + o * 25;
        float acc = pb[o] + pos[(t + 1) * 64 + o];
        #pragma unroll
        for (int p = 0; p < 25; p++) acc += xr[p] * wr[p];
        xo[(t + 1) * 64 + o] = acc;
    }
}

// K6: LN1 + QKV (64->192), 256 threads, 4x6 blocking
__global__ void __launch_bounds__(256) k_qkv(int l, const float* __restrict__ lg,
                      const float* __restrict__ lb, const float* __restrict__ w) {
    extern __shared__ float sm[];
    float* s_w  = sm;            // 192 rows * 66
    float* s_xn = sm + 12672;    // 32 rows * 66
    int b = blockIdx.x, tbase = blockIdx.y * 32, tid = threadIdx.x;
    int warp = tid >> 5, lane = tid & 31;
    for (int i = tid; i < 12288; i += 256)
        s_w[(i >> 6) * 66 + (i & 63)] = w[l * 12288 + i];
    if (warp < 8) {
        #pragma unroll
        for (int tt = 0; tt < 4; tt++) {
            int t = warp * 4 + tt, tg = tbase + t;
            float2 v = make_float2(0.f, 0.f);
            if (tg < 301) v = *(const float2*)(g_x + (b * 301 + tg) * 64 + lane * 2);
            float s = v.x + v.y;
            #pragma unroll
            for (int o = 16; o; o >>= 1) s += __shfl_xor_sync(0xffffffffu, s, o);
            float m = s * (1.f / 64.f);
            float d0 = v.x - m, d1 = v.y - m;
            float sq = d0 * d0 + d1 * d1;
            #pragma unroll
            for (int o = 16; o; o >>= 1) sq += __shfl_xor_sync(0xffffffffu, sq, o);
            float rstd = rsqrtf(sq * (1.f / 64.f) + 1e-5f);
            s_xn[t * 66 + lane * 2]     = d0 * rstd * lg[l * 64 + lane * 2]     + lb[l * 64 + lane * 2];
            s_xn[t * 66 + lane * 2 + 1] = d1 * rstd * lg[l * 64 + lane * 2 + 1] + lb[l * 64 + lane * 2 + 1];
        }
    }
    __syncthreads();
    int t0 = tid & 7, j0 = (tid >> 3) * 6;
    float2 acc[4][6];
    #pragma unroll
    for (int m = 0; m < 4; m++)
    #pragma unroll
    for (int n = 0; n < 6; n++) acc[m][n] = make_float2(0.f, 0.f);
    const float2* x2 = (const float2*)s_xn;
    const float2* w2 = (const float2*)s_w;
    #pragma unroll 4
    for (int k = 0; k < 32; k++) {
        float2 xv[4], wv[6];
        #pragma unroll
        for (int m = 0; m < 4; m++) xv[m] = x2[(t0 + 8 * m) * 33 + k];
        #pragma unroll
        for (int n = 0; n < 6; n++) wv[n] = w2[(j0 + n) * 33 + k];
        #pragma unroll
        for (int m = 0; m < 4; m++)
        #pragma unroll
        for (int n = 0; n < 6; n++) acc[m][n] = ffma2(xv[m], wv[n], acc[m][n]);
    }
    #pragma unroll
    for (int m = 0; m < 4; m++) {
        int tg = tbase + t0 + 8 * m;
        if (tg < 301) {
            float* op = g_qkv + (b * 301 + tg) * 192 + j0;
            #pragma unroll
            for (int n = 0; n < 3; n++) {
                float2 r = make_float2(acc[m][2 * n].x + acc[m][2 * n].y,
                                       acc[m][2 * n + 1].x + acc[m][2 * n + 1].y);
                *(float2*)(op + 2 * n) = r;
            }
        }
    }
}

// K7: attention per (b, head), d-split: one row per thread PAIR
// (even lane = dims 0-7, odd lane = dims 8-15; half-dots combined via shfl)
__global__ void __launch_bounds__(608) k_attn() {
    __shared__ float sK[301 * 20], sV[301 * 20];   // stride 20 -> 16B-aligned rows
    int b = blockIdx.x, h = blockIdx.y, tid = threadIdx.x;
    const float* qkv = g_qkv + b * 301 * 192;
    for (int i = tid; i < 1204; i += 608) {
        int j = i >> 2, dq = (i & 3) * 4;
        *(float4*)(sK + j * 20 + dq) = *(const float4*)(qkv + j * 192 + 64 + h * 16 + dq);
        *(float4*)(sV + j * 20 + dq) = *(const float4*)(qkv + j * 192 + 128 + h * 16 + dq);
    }
    __syncthreads();
    int p = tid >> 1, half = tid & 1;
    int row = (p < 301) ? p : 300;        // clamp; idle pairs recompute row 300
    int dbase = half * 8;
    float2 q[4];
    {
        const float4* qp = (const float4*)(qkv + row * 192 + h * 16 + dbase);
        float4 a0 = qp[0], a1 = qp[1];
        q[0] = make_float2(a0.x * 0.25f, a0.y * 0.25f);
        q[1] = make_float2(a0.z * 0.25f, a0.w * 0.25f);
        q[2] = make_float2(a1.x * 0.25f, a1.y * 0.25f);
        q[3] = make_float2(a1.z * 0.25f, a1.w * 0.25f);
    }
    float l = 0.f;
    float2 o[4];
    #pragma unroll
    for (int i = 0; i < 4; i++) o[i] = make_float2(0.f, 0.f);
    for (int j = 0; j < 301; j++) {
        const float4* kr = (const float4*)(sK + j * 20 + dbase);
        float4 k0 = kr[0], k1 = kr[1];
        float2 da = make_float2(0.f, 0.f), db = make_float2(0.f, 0.f);
        da = ffma2(q[0], make_float2(k0.x, k0.y), da);
        db = ffma2(q[1], make_float2(k0.z, k0.w), db);
        da = ffma2(q[2], make_float2(k1.x, k1.y), da);
        db = ffma2(q[3], make_float2(k1.z, k1.w), db);
        float hd = (da.x + db.x) + (da.y + db.y);
        float other = __shfl_xor_sync(0xffffffffu, hd, 1);
        float pe = __expf(hd + other);
        l += pe;
        float2 pv = make_float2(pe, pe);
        const float4* vr = (const float4*)(sV + j * 20 + dbase);
        float4 v0 = vr[0], v1 = vr[1];
        o[0] = ffma2(pv, make_float2(v0.x, v0.y), o[0]);
        o[1] = ffma2(pv, make_float2(v0.z, v0.w), o[1]);
        o[2] = ffma2(pv, make_float2(v1.x, v1.y), o[2]);
        o[3] = ffma2(pv, make_float2(v1.z, v1.w), o[3]);
    }
    if (p < 301) {
        float inv = 1.f / l;
        float4* op = (float4*)(g_o + (b * 301 + row) * 64 + h * 16 + dbase);
        op[0] = make_float4(o[0].x * inv, o[0].y * inv, o[1].x * inv, o[1].y * inv);
        op[1] = make_float4(o[2].x * inv, o[2].y * inv, o[3].x * inv, o[3].y * inv);
    }
}

// K8: out projection + residual, 128 threads, 4x4 blocking
__global__ void __launch_bounds__(128) k_proj(int l, const float* __restrict__ W,
                                              const float* __restrict__ B) {
    __shared__ float s_w[64 * 66], s_o[32 * 66];
    int b = blockIdx.x, tbase = blockIdx.y * 32, tid = threadIdx.x;
    for (int i = tid; i < 4096; i += 128) {
        int j = i >> 6, k = i & 63;
        s_w[j * 66 + k] = W[l * 4096 + i];
    }
    for (int i = tid; i < 2048; i += 128) {
        int t = i >> 6, k = i & 63, tg = tbase + t;
        s_o[t * 66 + k] = (tg < 301) ? g_o[(b * 301 + tg) * 64 + k] : 0.f;
    }
    __syncthreads();
    int t0 = tid & 7, j0 = (tid >> 3) * 4;
    float2 acc[4][4];
    #pragma unroll
    for (int m = 0; m < 4; m++)
    #pragma unroll
    for (int n = 0; n < 4; n++) acc[m][n] = make_float2(0.f, 0.f);
    const float2* x2 = (const float2*)s_o;
    const float2* w2 = (const float2*)s_w;
    #pragma unroll 4
    for (int k = 0; k < 32; k++) {
        float2 xv[4], wv[4];
        #pragma unroll
        for (int m = 0; m < 4; m++) xv[m] = x2[(t0 + 8 * m) * 33 + k];
        #pragma unroll
        for (int n = 0; n < 4; n++) wv[n] = w2[(j0 + n) * 33 + k];
        #pragma unroll
        for (int m = 0; m < 4; m++)
        #pragma unroll
        for (int n = 0; n < 4; n++) acc[m][n] = ffma2(xv[m], wv[n], acc[m][n]);
    }
    float4 bb = *(const float4*)(B + l * 64 + j0);
    #pragma unroll
    for (int m = 0; m < 4; m++) {
        int tg = tbase + t0 + 8 * m;
        if (tg < 301) {
            float4* xp = (float4*)(g_x + (b * 301 + tg) * 64 + j0);
            float4 v = *xp;
            v.x += acc[m][0].x + acc[m][0].y + bb.x;
            v.y += acc[m][1].x + acc[m][1].y + bb.y;
            v.z += acc[m][2].x + acc[m][2].y + bb.z;
            v.w += acc[m][3].x + acc[m][3].y + bb.w;
            *xp = v;
        }
    }
}

// K9: LN2 + MLP + residual
__global__ void k_ff(int l, const float* __restrict__ lg, const float* __restrict__ lb,
                     const float* __restrict__ w1, const float* __restrict__ b1,
                     const float* __restrict__ w2, const float* __restrict__ b2) {
    __shared__ float s_w1[512], s_w2[512], s_b1[8], s_b2[64], s_g[64], s_bb[64];
    int tid = threadIdx.x;
    for (int i = tid; i < 512; i += 256) { s_w1[i] = w1[l * 512 + i]; s_w2[i] = w2[l * 512 + i]; }
    if (tid < 8)  s_b1[tid] = b1[l * 8 + tid];
    if (tid < 64) { s_b2[tid] = b2[l * 64 + tid]; s_g[tid] = lg[l * 64 + tid]; s_bb[tid] = lb[l * 64 + tid]; }
    __syncthreads();
    int gid = blockIdx.x * 256 + tid;
    float* xr = g_x + gid * 64;
    float xv[64];
    float4* x4 = (float4*)xr;
    #pragma unroll
    for (int i = 0; i < 16; i++) {
        float4 v = x4[i];
        xv[4 * i] = v.x; xv[4 * i + 1] = v.y; xv[4 * i + 2] = v.z; xv[4 * i + 3] = v.w;
    }
    float s = 0.f;
    #pragma unroll
    for (int k = 0; k < 64; k++) s += xv[k];
    float m = s * (1.f / 64.f), sq = 0.f;
    #pragma unroll
    for (int k = 0; k < 64; k++) { float d = xv[k] - m; sq += d * d; }
    float rstd = rsqrtf(sq * (1.f / 64.f) + 1e-5f);
    float hid[8];
    #pragma unroll
    for (int mm = 0; mm < 8; mm++) hid[mm] = s_b1[mm];
    #pragma unroll
    for (int k = 0; k < 64; k++) {
        float xn = (xv[k] - m) * rstd * s_g[k] + s_bb[k];
        #pragma unroll
        for (int mm = 0; mm < 8; mm++) hid[mm] += xn * s_w1[mm * 64 + k];
    }
    #pragma unroll
    for (int mm = 0; mm < 8; mm++) {
        float hv = hid[mm];
        hid[mm] = 0.5f * hv * (1.f + erff(hv * 0.70710678118654752f));
    }
    #pragma unroll
    for (int k = 0; k < 64; k++) {
        float acc = s_b2[k];
        #pragma unroll
        for (int mm = 0; mm < 8; mm++) acc += hid[mm] * s_w2[k * 8 + mm];
        xv[k] += acc;
    }
    #pragma unroll
    for (int i = 0; i < 16; i++)
        x4[i] = make_float4(xv[4 * i], xv[4 * i + 1], xv[4 * i + 2], xv[4 * i + 3]);
}

// K10: head
__global__ void k_head(const float* __restrict__ hg, const float* __restrict__ hb,
                       const float* __restrict__ W, const float* __restrict__ B,
                       float* __restrict__ out) {
    __shared__ float s_z[128], s_red[8];
    int b = blockIdx.x, tid = threadIdx.x;
    int warp = tid >> 5, lane = tid & 31;
    float z = (tid < 64) ? g_x[b * 301 * 64 + tid] : g_y[b * 64 + tid - 64];
    float s = z;
    #pragma unroll
    for (int o = 16; o; o >>= 1) s += __shfl_xor_sync(0xffffffffu, s, o);
    if (lane == 0) s_red[warp] = s;
    __syncthreads();
    float m = (s_red[0] + s_red[1] + s_red[2] + s_red[3]) * (1.f / 128.f);
    float d = z - m, sq = d * d;
    #pragma unroll
    for (int o = 16; o; o >>= 1) sq += __shfl_xor_sync(0xffffffffu, sq, o);
    if (lane == 0) s_red[4 + warp] = sq;
    __syncthreads();
    float var = (s_red[4] + s_red[5] + s_red[6] + s_red[7]) * (1.f / 128.f);
    float rstd = rsqrtf(var + 1e-5f);
    s_z[tid] = d * rstd * hg[tid] + hb[tid];
    __syncthreads();
    if (tid < 16) {
        float acc = B[tid];
        const float* wr = W + tid * 128;
        #pragma unroll 16
        for (int k = 0; k < 128; k++) acc += s_z[k] * wr[k];
        out[b * 16 + tid] = acc;
    }
}

extern "C" void kernel_launch(void* const* d_in, const int* in_sizes, int n_in,
                              void* d_out, int out_size) {
    const float* input   = (const float*)d_in[0];
    const float* sse_w   = (const float*)d_in[1];
    const float* sse_b   = (const float*)d_in[2];
    const float* conv1_w = (const float*)d_in[3];
    const float* conv1_b = (const float*)d_in[4];
    const float* conv2_w = (const float*)d_in[5];
    const float* conv2_b = (const float*)d_in[6];
    const float* dense1_w= (const float*)d_in[7];
    const float* dense1_b= (const float*)d_in[8];
    const float* patch_w = (const float*)d_in[9];
    const float* patch_b = (const float*)d_in[10];
    const float* cls_tok = (const float*)d_in[11];
    const float* pos_emb = (const float*)d_in[12];
    const float* ln1_g   = (const float*)d_in[13];
    const float* ln1_b   = (const float*)d_in[14];
    const float* qkv_w   = (const float*)d_in[15];
    const float* ao_w    = (const float*)d_in[16];
    const float* ao_b    = (const float*)d_in[17];
    const float* ln2_g   = (const float*)d_in[18];
    const float* ln2_b   = (const float*)d_in[19];
    const float* ff1_w   = (const float*)d_in[20];
    const float* ff1_b   = (const float*)d_in[21];
    const float* ff2_w   = (const float*)d_in[22];
    const float* ff2_b   = (const float*)d_in[23];
    const float* hln_g   = (const float*)d_in[24];
    const float* hln_b   = (const float*)d_in[25];
    const float* head_w  = (const float*)d_in[26];
    const float* head_b  = (const float*)d_in[27];
    float* out = (float*)d_out;

    static bool attr_done = false;
    if (!attr_done) {
        cudaFuncSetAttribute(k_conv2, cudaFuncAttributeMaxDynamicSharedMemorySize, 197056);
        cudaFuncSetAttribute(k_qkv,   cudaFuncAttributeMaxDynamicSharedMemorySize, 59136);
        attr_done = true;
    }

    k_sse<<<512, 256>>>(input, sse_w, sse_b);                            // #1
    k_patch<<<512, 256>>>(patch_w, patch_b, cls_tok, pos_emb);           // #2
    for (int l = 0; l < 5; l++) {
        k_qkv<<<dim3(512, 10), 256, 59136>>>(l, ln1_g, ln1_b, qkv_w);    // #3 (l=0)
        k_attn<<<dim3(512, 4), 608>>>();                                 // #4 (l=0) -> profiled
        k_proj<<<dim3(512, 10), 128>>>(l, ao_w, ao_b);
        k_ff<<<602, 256>>>(l, ln2_g, ln2_b, ff1_w, ff1_b, ff2_w, ff2_b);
    }
    k_conv1<<<512, 256>>>(conv1_w, conv1_b);
    k_conv2<<<512, 256, 197056>>>(conv2_w, conv2_b);
    k_dense1<<<dim3(32, 16), 256>>>(dense1_w);
    k_yred<<<128, 256>>>(dense1_b);
    k_head<<<512, 128>>>(hln_g, hln_b, head_w, head_b, out);
}

// round 13
// speedup vs baseline: 1.1387x; 1.1387x over previous
#include <cuda_runtime.h>
#include <cuda_bf16.h>
#include <cstring>
#include <math.h>

static __device__ float g_xs[512 * 7500];
static __device__ float g_h1[512 * 42336];
static __device__ float g_h2[512 * 9344];
static __device__ float g_ypart[16 * 512 * 64];
static __device__ float g_y[512 * 64];
static __device__ float g_x[512 * 301 * 64];
static __device__ float g_qkv[512 * 301 * 192];   // token-major [b][301][192]
static __device__ float g_o[512 * 301 * 64];

__device__ __forceinline__ float2 ffma2(float2 a, float2 b, float2 c) {
    unsigned long long ua, ub, uc, ud;
    memcpy(&ua, &a, 8); memcpy(&ub, &b, 8); memcpy(&uc, &c, 8);
    asm("fma.rn.f32x2 %0, %1, %2, %3;" : "=l"(ud) : "l"(ua), "l"(ub), "l"(uc));
    float2 d; memcpy(&d, &ud, 8);
    return d;
}

// K1: SSE gate
__global__ void k_sse(const float* __restrict__ in, const float* __restrict__ sw,
                      const float* __restrict__ sb) {
    int b = blockIdx.x, tid = threadIdx.x;
    __shared__ float s_w[300], s_g[25];
    const float* x = in + b * 7500;
    for (int i = tid; i < 300; i += 256) s_w[i] = sw[i];
    __syncthreads();
    int warp = tid >> 5, lane = tid & 31;
    for (int p = warp; p < 25; p += 8) {
        float acc = 0.f;
        const float* xp = x + p * 300;
        for (int c = lane; c < 300; c += 32) acc += xp[c] * s_w[c];
        #pragma unroll
        for (int o = 16; o; o >>= 1) acc += __shfl_xor_sync(0xffffffffu, acc, o);
        if (lane == 0) s_g[p] = 1.f / (1.f + expf(-(acc + sb[0])));
    }
    __syncthreads();
    float* xo = g_xs + b * 7500;
    for (int i = tid; i < 7500; i += 256) xo[i] = x[i] * s_g[i / 300];
}

// K2: conv1 (1->16, 3x3x7) + relu
__global__ void k_conv1(const float* __restrict__ W, const float* __restrict__ B) {
    int b = blockIdx.x, tid = threadIdx.x;
    __shared__ float sx[7552], sw[1008], sb[16];
    const float* xs = g_xs + b * 7500;
    for (int i = tid; i < 7552; i += 256) sx[i] = (i < 7500) ? xs[i] : 0.f;
    for (int i = tid; i < 1008; i += 256) sw[i] = W[i];
    if (tid < 16) sb[tid] = B[tid];
    __syncthreads();
    float* out = g_h1 + b * 42336;
    int warp = tid >> 5, lane = tid & 31, w0 = lane * 10;
    for (int row = warp; row < 144; row += 8) {
        int o = row / 9, dh = row % 9, d = dh / 3, hh = dh % 3;
        const float* wp = sw + o * 63;
        float acc[10];
        #pragma unroll
        for (int u = 0; u < 10; u++) acc[u] = sb[o];
        #pragma unroll
        for (int kd = 0; kd < 3; kd++)
        #pragma unroll
        for (int kh = 0; kh < 3; kh++) {
            const float* ip = sx + (d + kd) * 1500 + (hh + kh) * 300 + w0;
            float iv[16];
            #pragma unroll
            for (int u = 0; u < 16; u++) iv[u] = ip[u];
            const float* wq = wp + kd * 21 + kh * 7;
            #pragma unroll
            for (int kw = 0; kw < 7; kw++) {
                float wv = wq[kw];
                #pragma unroll
                for (int u = 0; u < 10; u++) acc[u] += iv[u + kw] * wv;
            }
        }
        #pragma unroll
        for (int u = 0; u < 10; u++)
            if (w0 + u < 294) out[row * 294 + w0 + u] = fmaxf(acc[u], 0.f);
    }
}

// K3: conv2 (16->32, 3x3x3) + relu, W-tiled grid (512, 4)
__global__ void k_conv2(const float* __restrict__ W, const float* __restrict__ B) {
    extern __shared__ float sm[];
    float* s_in = sm;             // 144 * 76 = 10944
    float* s_w  = sm + 10944;     // 32 * 433 = 13856
    int b = blockIdx.x, w0 = blockIdx.y * 73, tid = threadIdx.x;
    const float* hin = g_h1 + b * 42336;
    for (int i = tid; i < 10944; i += 256) {
        int row = i / 76, c = i % 76;
        s_in[i] = (w0 + c < 294) ? hin[row * 294 + w0 + c] : 0.f;
    }
    for (int i = tid; i < 13824; i += 256)
        s_w[(i / 432) * 433 + (i % 432)] = W[i];
    __syncthreads();
    float* out = g_h2 + b * 9344;
    for (int t = tid; t < 608; t += 256) {
        int oc = t & 31, wl = (t >> 5) * 4;
        const float* wp = s_w + oc * 433;
        float a0 = 0.f, a1 = 0.f, a2 = 0.f, a3 = 0.f;
        for (int ic = 0; ic < 16; ic++)
        #pragma unroll
        for (int kd = 0; kd < 3; kd++)
        #pragma unroll
        for (int kh = 0; kh < 3; kh++) {
            const float* ip = s_in + (ic * 9 + kd * 3 + kh) * 76 + wl;
            float i0 = ip[0], i1 = ip[1], i2 = ip[2];
            float i3 = ip[3], i4 = ip[4], i5 = ip[5];
            const float* wq = wp + (ic * 9 + kd * 3 + kh) * 3;
            float v0 = wq[0], v1 = wq[1], v2 = wq[2];
            a0 += i0 * v0 + i1 * v1 + i2 * v2;
            a1 += i1 * v0 + i2 * v1 + i3 * v2;
            a2 += i2 * v0 + i3 * v1 + i4 * v2;
            a3 += i3 * v0 + i4 * v1 + i5 * v2;
        }
        float bb = B[oc];
        float r[4] = {a0, a1, a2, a3};
        #pragma unroll
        for (int u = 0; u < 4; u++)
            if (wl + u < 73) out[oc * 292 + w0 + wl + u] = fmaxf(r[u] + bb, 0.f);
    }
}

// K4: dense1 (9344->64), split-K 16
__global__ void k_dense1(const float* __restrict__ W) {
    __shared__ float sA[16][33], sB[64][33];
    int rb = blockIdx.x * 16, kc = blockIdx.y * 584, tid = threadIdx.x;
    int r = tid & 15, cg = tid >> 4;
    float a0 = 0.f, a1 = 0.f, a2 = 0.f, a3 = 0.f;
    for (int k0 = 0; k0 < 584; k0 += 32) {
        int kw = 584 - k0 < 32 ? 584 - k0 : 32;
        for (int i = tid; i < 512; i += 256) {
            int col = i & 31;
            sA[i >> 5][col] = (col < kw) ? g_h2[(rb + (i >> 5)) * 9344 + kc + k0 + col] : 0.f;
        }
        for (int i = tid; i < 2048; i += 256) {
            int col = i & 31;
            sB[i >> 5][col] = (col < kw) ? W[(i >> 5) * 9344 + kc + k0 + col] : 0.f;
        }
        __syncthreads();
        #pragma unroll
        for (int kk = 0; kk < 32; kk++) {
            float a = sA[r][kk];
            a0 += a * sB[cg * 4 + 0][kk];
            a1 += a * sB[cg * 4 + 1][kk];
            a2 += a * sB[cg * 4 + 2][kk];
            a3 += a * sB[cg * 4 + 3][kk];
        }
        __syncthreads();
    }
    float* yp = g_ypart + blockIdx.y * 32768 + (rb + r) * 64 + cg * 4;
    yp[0] = a0; yp[1] = a1; yp[2] = a2; yp[3] = a3;
}

__global__ void k_yred(const float* __restrict__ bias) {
    int i = blockIdx.x * 256 + threadIdx.x;
    float acc = bias[i & 63];
    #pragma unroll
    for (int s = 0; s < 16; s++) acc += g_ypart[s * 32768 + i];
    g_y[i] = acc;
}

// K5: patch embed + cls + pos
__global__ void k_patch(const float* __restrict__ pw, const float* __restrict__ pb,
                        const float* __restrict__ cls, const float* __restrict__ pos) {
    __shared__ float s_x[7500], s_w[1600];
    int b = blockIdx.x, tid = threadIdx.x;
    const float* xs = g_xs + b * 7500;
    for (int i = tid; i < 7500; i += 256) s_x[i] = xs[i];
    for (int i = tid; i < 1600; i += 256) s_w[i] = pw[i];
    __syncthreads();
    float* xo = g_x + b * 301 * 64;
    if (tid < 64) xo[tid] = cls[tid] + pos[tid];
    for (int idx = tid; idx < 19200; idx += 256) {
        int t = idx >> 6, o = idx & 63;
        const float* xr = s_x + t * 25;
        const float* wr = s_w + o * 25;
        float acc = pb[o] + pos[(t + 1) * 64 + o];
        #pragma unroll
        for (int p = 0; p < 25; p++) acc += xr[p] * wr[p];
        xo[(t + 1) * 64 + o] = acc;
    }
}

// K6: LN1 + QKV (64->192), 256 threads, 4x6 blocking
__global__ void __launch_bounds__(256) k_qkv(int l, const float* __restrict__ lg,
                      const float* __restrict__ lb, const float* __restrict__ w) {
    extern __shared__ float sm[];
    float* s_w  = sm;            // 192 rows * 66
    float* s_xn = sm + 12672;    // 32 rows * 66
    int b = blockIdx.x, tbase = blockIdx.y * 32, tid = threadIdx.x;
    int warp = tid >> 5, lane = tid & 31;
    for (int i = tid; i < 12288; i += 256)
        s_w[(i >> 6) * 66 + (i & 63)] = w[l * 12288 + i];
    if (warp < 8) {
        #pragma unroll
        for (int tt = 0; tt < 4; tt++) {
            int t = warp * 4 + tt, tg = tbase + t;
            float2 v = make_float2(0.f, 0.f);
            if (tg < 301) v = *(const float2*)(g_x + (b * 301 + tg) * 64 + lane * 2);
            float s = v.x + v.y;
            #pragma unroll
            for (int o = 16; o; o >>= 1) s += __shfl_xor_sync(0xffffffffu, s, o);
            float m = s * (1.f / 64.f);
            float d0 = v.x - m, d1 = v.y - m;
            float sq = d0 * d0 + d1 * d1;
            #pragma unroll
            for (int o = 16; o; o >>= 1) sq += __shfl_xor_sync(0xffffffffu, sq, o);
            float rstd = rsqrtf(sq * (1.f / 64.f) + 1e-5f);
            s_xn[t * 66 + lane * 2]     = d0 * rstd * lg[l * 64 + lane * 2]     + lb[l * 64 + lane * 2];
            s_xn[t * 66 + lane * 2 + 1] = d1 * rstd * lg[l * 64 + lane * 2 + 1] + lb[l * 64 + lane * 2 + 1];
        }
    }
    __syncthreads();
    int t0 = tid & 7, j0 = (tid >> 3) * 6;
    float2 acc[4][6];
    #pragma unroll
    for (int m = 0; m < 4; m++)
    #pragma unroll
    for (int n = 0; n < 6; n++) acc[m][n] = make_float2(0.f, 0.f);
    const float2* x2 = (const float2*)s_xn;
    const float2* w2 = (const float2*)s_w;
    #pragma unroll 4
    for (int k = 0; k < 32; k++) {
        float2 xv[4], wv[6];
        #pragma unroll
        for (int m = 0; m < 4; m++) xv[m] = x2[(t0 + 8 * m) * 33 + k];
        #pragma unroll
        for (int n = 0; n < 6; n++) wv[n] = w2[(j0 + n) * 33 + k];
        #pragma unroll
        for (int m = 0; m < 4; m++)
        #pragma unroll
        for (int n = 0; n < 6; n++) acc[m][n] = ffma2(xv[m], wv[n], acc[m][n]);
    }
    #pragma unroll
    for (int m = 0; m < 4; m++) {
        int tg = tbase + t0 + 8 * m;
        if (tg < 301) {
            float* op = g_qkv + (b * 301 + tg) * 192 + j0;
            #pragma unroll
            for (int n = 0; n < 3; n++) {
                float2 r = make_float2(acc[m][2 * n].x + acc[m][2 * n].y,
                                       acc[m][2 * n + 1].x + acc[m][2 * n + 1].y);
                *(float2*)(op + 2 * n) = r;
            }
        }
    }
}

// K7: attention per (b, head), R=2 rows/thread, 160 threads,
// K staged as bf16 in smem (half crossbar bytes, stride 12 for 16B alignment);
// V stays fp32.
__global__ void __launch_bounds__(160) k_attn() {
    __shared__ unsigned sKb[301 * 12];             // 8 used + 4 pad per row; rows 48B-aligned
    __shared__ float sV[301 * 20];                 // fp32, stride 20
    int b = blockIdx.x, h = blockIdx.y, tid = threadIdx.x;
    const float* qkv = g_qkv + b * 301 * 192;
    for (int i = tid; i < 1204; i += 160) {
        int j = i >> 2, dq = (i & 3) * 4;
        float4 kv = *(const float4*)(qkv + j * 192 + 64 + h * 16 + dq);
        __nv_bfloat162 p0 = __floats2bfloat162_rn(kv.x, kv.y);
        __nv_bfloat162 p1 = __floats2bfloat162_rn(kv.z, kv.w);
        unsigned u0, u1;
        memcpy(&u0, &p0, 4); memcpy(&u1, &p1, 4);
        *(uint2*)(sKb + j * 12 + (i & 3) * 2) = make_uint2(u0, u1);
        *(float4*)(sV + j * 20 + dq) = *(const float4*)(qkv + j * 192 + 128 + h * 16 + dq);
    }
    __syncthreads();
    if (tid > 150) return;
    int r0 = tid, r1 = tid + 151;
    bool has2 = (r1 <= 300);
    float2 q0[8], q1[8];
    {
        const float4* qp = (const float4*)(qkv + r0 * 192 + h * 16);
        #pragma unroll
        for (int i = 0; i < 4; i++) {
            float4 a = qp[i];
            q0[2 * i]     = make_float2(a.x * 0.25f, a.y * 0.25f);
            q0[2 * i + 1] = make_float2(a.z * 0.25f, a.w * 0.25f);
        }
        if (has2) {
            const float4* qp1 = (const float4*)(qkv + r1 * 192 + h * 16);
            #pragma unroll
            for (int i = 0; i < 4; i++) {
                float4 a = qp1[i];
                q1[2 * i]     = make_float2(a.x * 0.25f, a.y * 0.25f);
                q1[2 * i + 1] = make_float2(a.z * 0.25f, a.w * 0.25f);
            }
        } else {
            #pragma unroll
            for (int i = 0; i < 8; i++) q1[i] = make_float2(0.f, 0.f);
        }
    }
    float l0 = 0.f, l1 = 0.f;
    float2 o0[8], o1[8];
    #pragma unroll
    for (int i = 0; i < 8; i++) { o0[i] = make_float2(0.f, 0.f); o1[i] = make_float2(0.f, 0.f); }
    for (int j = 0; j < 301; j++) {
        const uint4* kbp = (const uint4*)(sKb + j * 12);
        uint4 ka = kbp[0], kb = kbp[1];
        float2 d0 = make_float2(0.f, 0.f), d1 = d0;
        unsigned uu[8] = {ka.x, ka.y, ka.z, ka.w, kb.x, kb.y, kb.z, kb.w};
        #pragma unroll
        for (int i = 0; i < 8; i++) {
            float2 kvp = make_float2(__uint_as_float(uu[i] << 16),
                                     __uint_as_float(uu[i] & 0xFFFF0000u));
            d0 = ffma2(q0[i], kvp, d0);
            d1 = ffma2(q1[i], kvp, d1);
        }
        float p0 = __expf(d0.x + d0.y);
        float p1 = __expf(d1.x + d1.y);
        l0 += p0; l1 += p1;
        float2 pa = make_float2(p0, p0), pb = make_float2(p1, p1);
        const float4* vr = (const float4*)(sV + j * 20);
        float4 v0 = vr[0], v1 = vr[1], v2 = vr[2], v3 = vr[3];
        float2 vlo0 = make_float2(v0.x, v0.y), vhi0 = make_float2(v0.z, v0.w);
        float2 vlo1 = make_float2(v1.x, v1.y), vhi1 = make_float2(v1.z, v1.w);
        float2 vlo2 = make_float2(v2.x, v2.y), vhi2 = make_float2(v2.z, v2.w);
        float2 vlo3 = make_float2(v3.x, v3.y), vhi3 = make_float2(v3.z, v3.w);
        o0[0] = ffma2(pa, vlo0, o0[0]); o0[1] = ffma2(pa, vhi0, o0[1]);
        o0[2] = ffma2(pa, vlo1, o0[2]); o0[3] = ffma2(pa, vhi1, o0[3]);
        o0[4] = ffma2(pa, vlo2, o0[4]); o0[5] = ffma2(pa, vhi2, o0[5]);
        o0[6] = ffma2(pa, vlo3, o0[6]); o0[7] = ffma2(pa, vhi3, o0[7]);
        o1[0] = ffma2(pb, vlo0, o1[0]); o1[1] = ffma2(pb, vhi0, o1[1]);
        o1[2] = ffma2(pb, vlo1, o1[2]); o1[3] = ffma2(pb, vhi1, o1[3]);
        o1[4] = ffma2(pb, vlo2, o1[4]); o1[5] = ffma2(pb, vhi2, o1[5]);
        o1[6] = ffma2(pb, vlo3, o1[6]); o1[7] = ffma2(pb, vhi3, o1[7]);
    }
    float inv0 = 1.f / l0;
    float2* op0 = (float2*)(g_o + (b * 301 + r0) * 64 + h * 16);
    #pragma unroll
    for (int i = 0; i < 8; i++) op0[i] = make_float2(o0[i].x * inv0, o0[i].y * inv0);
    if (has2) {
        float inv1 = 1.f / l1;
        float2* op1 = (float2*)(g_o + (b * 301 + r1) * 64 + h * 16);
        #pragma unroll
        for (int i = 0; i < 8; i++) op1[i] = make_float2(o1[i].x * inv1, o1[i].y * inv1);
    }
}

// K8: out projection + residual, 128 threads, 4x4 blocking
__global__ void __launch_bounds__(128) k_proj(int l, const float* __restrict__ W,
                                              const float* __restrict__ B) {
    __shared__ float s_w[64 * 66], s_o[32 * 66];
    int b = blockIdx.x, tbase = blockIdx.y * 32, tid = threadIdx.x;
    for (int i = tid; i < 4096; i += 128) {
        int j = i >> 6, k = i & 63;
        s_w[j * 66 + k] = W[l * 4096 + i];
    }
    for (int i = tid; i < 2048; i += 128) {
        int t = i >> 6, k = i & 63, tg = tbase + t;
        s_o[t * 66 + k] = (tg < 301) ? g_o[(b * 301 + tg) * 64 + k] : 0.f;
    }
    __syncthreads();
    int t0 = tid & 7, j0 = (tid >> 3) * 4;
    float2 acc[4][4];
    #pragma unroll
    for (int m = 0; m < 4; m++)
    #pragma unroll
    for (int n = 0; n < 4; n++) acc[m][n] = make_float2(0.f, 0.f);
    const float2* x2 = (const float2*)s_o;
    const float2* w2 = (const float2*)s_w;
    #pragma unroll 4
    for (int k = 0; k < 32; k++) {
        float2 xv[4], wv[4];
        #pragma unroll
        for (int m = 0; m < 4; m++) xv[m] = x2[(t0 + 8 * m) * 33 + k];
        #pragma unroll
        for (int n = 0; n < 4; n++) wv[n] = w2[(j0 + n) * 33 + k];
        #pragma unroll
        for (int m = 0; m < 4; m++)
        #pragma unroll
        for (int n = 0; n < 4; n++) acc[m][n] = ffma2(xv[m], wv[n], acc[m][n]);
    }
    float4 bb = *(const float4*)(B + l * 64 + j0);
    #pragma unroll
    for (int m = 0; m < 4; m++) {
        int tg = tbase + t0 + 8 * m;
        if (tg < 301) {
            float4* xp = (float4*)(g_x + (b * 301 + tg) * 64 + j0);
            float4 v = *xp;
            v.x += acc[m][0].x + acc[m][0].y + bb.x;
            v.y += acc[m][1].x + acc[m][1].y + bb.y;
            v.z += acc[m][2].x + acc[m][2].y + bb.z;
            v.w += acc[m][3].x + acc[m][3].y + bb.w;
            *xp = v;
        }
    }
}

// K9: LN2 + MLP + residual
__global__ void k_ff(int l, const float* __restrict__ lg, const float* __restrict__ lb,
                     const float* __restrict__ w1, const float* __restrict__ b1,
                     const float* __restrict__ w2, const float* __restrict__ b2) {
    __shared__ float s_w1[512], s_w2[512], s_b1[8], s_b2[64], s_g[64], s_bb[64];
    int tid = threadIdx.x;
    for (int i = tid; i < 512; i += 256) { s_w1[i] = w1[l * 512 + i]; s_w2[i] = w2[l * 512 + i]; }
    if (tid < 8)  s_b1[tid] = b1[l * 8 + tid];
    if (tid < 64) { s_b2[tid] = b2[l * 64 + tid]; s_g[tid] = lg[l * 64 + tid]; s_bb[tid] = lb[l * 64 + tid]; }
    __syncthreads();
    int gid = blockIdx.x * 256 + tid;
    float* xr = g_x + gid * 64;
    float xv[64];
    float4* x4 = (float4*)xr;
    #pragma unroll
    for (int i = 0; i < 16; i++) {
        float4 v = x4[i];
        xv[4 * i] = v.x; xv[4 * i + 1] = v.y; xv[4 * i + 2] = v.z; xv[4 * i + 3] = v.w;
    }
    float s = 0.f;
    #pragma unroll
    for (int k = 0; k < 64; k++) s += xv[k];
    float m = s * (1.f / 64.f), sq = 0.f;
    #pragma unroll
    for (int k = 0; k < 64; k++) { float d = xv[k] - m; sq += d * d; }
    float rstd = rsqrtf(sq * (1.f / 64.f) + 1e-5f);
    float hid[8];
    #pragma unroll
    for (int mm = 0; mm < 8; mm++) hid[mm] = s_b1[mm];
    #pragma unroll
    for (int k = 0; k < 64; k++) {
        float xn = (xv[k] - m) * rstd * s_g[k] + s_bb[k];
        #pragma unroll
        for (int mm = 0; mm < 8; mm++) hid[mm] += xn * s_w1[mm * 64 + k];
    }
    #pragma unroll
    for (int mm = 0; mm < 8; mm++) {
        float hv = hid[mm];
        hid[mm] = 0.5f * hv * (1.f + erff(hv * 0.70710678118654752f));
    }
    #pragma unroll
    for (int k = 0; k < 64; k++) {
        float acc = s_b2[k];
        #pragma unroll
        for (int mm = 0; mm < 8; mm++) acc += hid[mm] * s_w2[k * 8 + mm];
        xv[k] += acc;
    }
    #pragma unroll
    for (int i = 0; i < 16; i++)
        x4[i] = make_float4(xv[4 * i], xv[4 * i + 1], xv[4 * i + 2], xv[4 * i + 3]);
}

// K10: head
__global__ void k_head(const float* __restrict__ hg, const float* __restrict__ hb,
                       const float* __restrict__ W, const float* __restrict__ B,
                       float* __restrict__ out) {
    __shared__ float s_z[128], s_red[8];
    int b = blockIdx.x, tid = threadIdx.x;
    int warp = tid >> 5, lane = tid & 31;
    float z = (tid < 64) ? g_x[b * 301 * 64 + tid] : g_y[b * 64 + tid - 64];
    float s = z;
    #pragma unroll
    for (int o = 16; o; o >>= 1) s += __shfl_xor_sync(0xffffffffu, s, o);
    if (lane == 0) s_red[warp] = s;
    __syncthreads();
    float m = (s_red[0] + s_red[1] + s_red[2] + s_red[3]) * (1.f / 128.f);
    float d = z - m, sq = d * d;
    #pragma unroll
    for (int o = 16; o; o >>= 1) sq += __shfl_xor_sync(0xffffffffu, sq, o);
    if (lane == 0) s_red[4 + warp] = sq;
    __syncthreads();
    float var = (s_red[4] + s_red[5] + s_red[6] + s_red[7]) * (1.f / 128.f);
    float rstd = rsqrtf(var + 1e-5f);
    s_z[tid] = d * rstd * hg[tid] + hb[tid];
    __syncthreads();
    if (tid < 16) {
        float acc = B[tid];
        const float* wr = W + tid * 128;
        #pragma unroll 16
        for (int k = 0; k < 128; k++) acc += s_z[k] * wr[k];
        out[b * 16 + tid] = acc;
    }
}

extern "C" void kernel_launch(void* const* d_in, const int* in_sizes, int n_in,
                              void* d_out, int out_size) {
    const float* input   = (const float*)d_in[0];
    const float* sse_w   = (const float*)d_in[1];
    const float* sse_b   = (const float*)d_in[2];
    const float* conv1_w = (const float*)d_in[3];
    const float* conv1_b = (const float*)d_in[4];
    const float* conv2_w = (const float*)d_in[5];
    const float* conv2_b = (const float*)d_in[6];
    const float* dense1_w= (const float*)d_in[7];
    const float* dense1_b= (const float*)d_in[8];
    const float* patch_w = (const float*)d_in[9];
    const float* patch_b = (const float*)d_in[10];
    const float* cls_tok = (const float*)d_in[11];
    const float* pos_emb = (const float*)d_in[12];
    const float* ln1_g   = (const float*)d_in[13];
    const float* ln1_b   = (const float*)d_in[14];
    const float* qkv_w   = (const float*)d_in[15];
    const float* ao_w    = (const float*)d_in[16];
    const float* ao_b    = (const float*)d_in[17];
    const float* ln2_g   = (const float*)d_in[18];
    const float* ln2_b   = (const float*)d_in[19];
    const float* ff1_w   = (const float*)d_in[20];
    const float* ff1_b   = (const float*)d_in[21];
    const float* ff2_w   = (const float*)d_in[22];
    const float* ff2_b   = (const float*)d_in[23];
    const float* hln_g   = (const float*)d_in[24];
    const float* hln_b   = (const float*)d_in[25];
    const float* head_w  = (const float*)d_in[26];
    const float* head_b  = (const float*)d_in[27];
    float* out = (float*)d_out;

    static bool attr_done = false;
    if (!attr_done) {
        cudaFuncSetAttribute(k_conv2, cudaFuncAttributeMaxDynamicSharedMemorySize, 99200);
        cudaFuncSetAttribute(k_qkv,   cudaFuncAttributeMaxDynamicSharedMemorySize, 59136);
        attr_done = true;
    }

    k_sse<<<512, 256>>>(input, sse_w, sse_b);                            // #1
    k_patch<<<512, 256>>>(patch_w, patch_b, cls_tok, pos_emb);           // #2
    for (int l = 0; l < 5; l++) {
        k_qkv<<<dim3(512, 10), 256, 59136>>>(l, ln1_g, ln1_b, qkv_w);    // #3 (l=0)
        k_attn<<<dim3(512, 4), 160>>>();                                 // #4 (l=0) -> profiled
        k_proj<<<dim3(512, 10), 128>>>(l, ao_w, ao_b);
        k_ff<<<602, 256>>>(l, ln2_g, ln2_b, ff1_w, ff1_b, ff2_w, ff2_b);
    }
    k_conv1<<<512, 256>>>(conv1_w, conv1_b);
    k_conv2<<<dim3(512, 4), 256, 99200>>>(conv2_w, conv2_b);
    k_dense1<<<dim3(32, 16), 256>>>(dense1_w);
    k_yred<<<128, 256>>>(dense1_b);
    k_head<<<512, 128>>>(hln_g, hln_b, head_w, head_b, out);
}

// round 14
// speedup vs baseline: 1.7927x; 1.5744x over previous
#include <cuda_runtime.h>
#include <cuda_bf16.h>
#include <cstring>
#include <math.h>

static __device__ float g_xs[512 * 7500];
static __device__ float g_h1[512 * 42336];
static __device__ float g_h2[512 * 9344];
static __device__ float g_ypart[16 * 512 * 64];
static __device__ float g_y[512 * 64];
static __device__ float g_x[512 * 301 * 64];
static __device__ float g_qkv[512 * 301 * 192];   // token-major [b][301][192]
static __device__ float g_o[512 * 301 * 64];

__device__ __forceinline__ float2 ffma2(float2 a, float2 b, float2 c) {
    unsigned long long ua, ub, uc, ud;
    memcpy(&ua, &a, 8); memcpy(&ub, &b, 8); memcpy(&uc, &c, 8);
    asm("fma.rn.f32x2 %0, %1, %2, %3;" : "=l"(ud) : "l"(ua), "l"(ub), "l"(uc));
    float2 d; memcpy(&d, &ud, 8);
    return d;
}

__device__ __forceinline__ unsigned packbf(float x, float y) {
    __nv_bfloat162 t = __floats2bfloat162_rn(x, y);
    unsigned u; memcpy(&u, &t, 4);
    return u;
}

__device__ __forceinline__ void mma16816(float* d, const unsigned* a,
                                         const unsigned* b, const float* c) {
    asm volatile(
        "mma.sync.aligned.m16n8k16.row.col.f32.bf16.bf16.f32 "
        "{%0,%1,%2,%3}, {%4,%5,%6,%7}, {%8,%9}, {%10,%11,%12,%13};"
        : "=f"(d[0]), "=f"(d[1]), "=f"(d[2]), "=f"(d[3])
        : "r"(a[0]), "r"(a[1]), "r"(a[2]), "r"(a[3]),
          "r"(b[0]), "r"(b[1]),
          "f"(c[0]), "f"(c[1]), "f"(c[2]), "f"(c[3]));
}

// K1: SSE gate
__global__ void k_sse(const float* __restrict__ in, const float* __restrict__ sw,
                      const float* __restrict__ sb) {
    int b = blockIdx.x, tid = threadIdx.x;
    __shared__ float s_w[300], s_g[25];
    const float* x = in + b * 7500;
    for (int i = tid; i < 300; i += 256) s_w[i] = sw[i];
    __syncthreads();
    int warp = tid >> 5, lane = tid & 31;
    for (int p = warp; p < 25; p += 8) {
        float acc = 0.f;
        const float* xp = x + p * 300;
        for (int c = lane; c < 300; c += 32) acc += xp[c] * s_w[c];
        #pragma unroll
        for (int o = 16; o; o >>= 1) acc += __shfl_xor_sync(0xffffffffu, acc, o);
        if (lane == 0) s_g[p] = 1.f / (1.f + expf(-(acc + sb[0])));
    }
    __syncthreads();
    float* xo = g_xs + b * 7500;
    for (int i = tid; i < 7500; i += 256) xo[i] = x[i] * s_g[i / 300];
}

// K2: conv1 (1->16, 3x3x7) + relu
__global__ void k_conv1(const float* __restrict__ W, const float* __restrict__ B) {
    int b = blockIdx.x, tid = threadIdx.x;
    __shared__ float sx[7552], sw[1008], sb[16];
    const float* xs = g_xs + b * 7500;
    for (int i = tid; i < 7552; i += 256) sx[i] = (i < 7500) ? xs[i] : 0.f;
    for (int i = tid; i < 1008; i += 256) sw[i] = W[i];
    if (tid < 16) sb[tid] = B[tid];
    __syncthreads();
    float* out = g_h1 + b * 42336;
    int warp = tid >> 5, lane = tid & 31, w0 = lane * 10;
    for (int row = warp; row < 144; row += 8) {
        int o = row / 9, dh = row % 9, d = dh / 3, hh = dh % 3;
        const float* wp = sw + o * 63;
        float acc[10];
        #pragma unroll
        for (int u = 0; u < 10; u++) acc[u] = sb[o];
        #pragma unroll
        for (int kd = 0; kd < 3; kd++)
        #pragma unroll
        for (int kh = 0; kh < 3; kh++) {
            const float* ip = sx + (d + kd) * 1500 + (hh + kh) * 300 + w0;
            float iv[16];
            #pragma unroll
            for (int u = 0; u < 16; u++) iv[u] = ip[u];
            const float* wq = wp + kd * 21 + kh * 7;
            #pragma unroll
            for (int kw = 0; kw < 7; kw++) {
                float wv = wq[kw];
                #pragma unroll
                for (int u = 0; u < 10; u++) acc[u] += iv[u + kw] * wv;
            }
        }
        #pragma unroll
        for (int u = 0; u < 10; u++)
            if (w0 + u < 294) out[row * 294 + w0 + u] = fmaxf(acc[u], 0.f);
    }
}

// K3: conv2 (16->32, 3x3x3) + relu, W-tiled grid (512, 4)
__global__ void k_conv2(const float* __restrict__ W, const float* __restrict__ B) {
    extern __shared__ float sm[];
    float* s_in = sm;             // 144 * 76 = 10944
    float* s_w  = sm + 10944;     // 32 * 433 = 13856
    int b = blockIdx.x, w0 = blockIdx.y * 73, tid = threadIdx.x;
    const float* hin = g_h1 + b * 42336;
    for (int i = tid; i < 10944; i += 256) {
        int row = i / 76, c = i % 76;
        s_in[i] = (w0 + c < 294) ? hin[row * 294 + w0 + c] : 0.f;
    }
    for (int i = tid; i < 13824; i += 256)
        s_w[(i / 432) * 433 + (i % 432)] = W[i];
    __syncthreads();
    float* out = g_h2 + b * 9344;
    for (int t = tid; t < 608; t += 256) {
        int oc = t & 31, wl = (t >> 5) * 4;
        const float* wp = s_w + oc * 433;
        float a0 = 0.f, a1 = 0.f, a2 = 0.f, a3 = 0.f;
        for (int ic = 0; ic < 16; ic++)
        #pragma unroll
        for (int kd = 0; kd < 3; kd++)
        #pragma unroll
        for (int kh = 0; kh < 3; kh++) {
            const float* ip = s_in + (ic * 9 + kd * 3 + kh) * 76 + wl;
            float i0 = ip[0], i1 = ip[1], i2 = ip[2];
            float i3 = ip[3], i4 = ip[4], i5 = ip[5];
            const float* wq = wp + (ic * 9 + kd * 3 + kh) * 3;
            float v0 = wq[0], v1 = wq[1], v2 = wq[2];
            a0 += i0 * v0 + i1 * v1 + i2 * v2;
            a1 += i1 * v0 + i2 * v1 + i3 * v2;
            a2 += i2 * v0 + i3 * v1 + i4 * v2;
            a3 += i3 * v0 + i4 * v1 + i5 * v2;
        }
        float bb = B[oc];
        float r[4] = {a0, a1, a2, a3};
        #pragma unroll
        for (int u = 0; u < 4; u++)
            if (wl + u < 73) out[oc * 292 + w0 + wl + u] = fmaxf(r[u] + bb, 0.f);
    }
}

// K4: dense1 (9344->64), split-K 16
__global__ void k_dense1(const float* __restrict__ W) {
    __shared__ float sA[16][33], sB[64][33];
    int rb = blockIdx.x * 16, kc = blockIdx.y * 584, tid = threadIdx.x;
    int r = tid & 15, cg = tid >> 4;
    float a0 = 0.f, a1 = 0.f, a2 = 0.f, a3 = 0.f;
    for (int k0 = 0; k0 < 584; k0 += 32) {
        int kw = 584 - k0 < 32 ? 584 - k0 : 32;
        for (int i = tid; i < 512; i += 256) {
            int col = i & 31;
            sA[i >> 5][col] = (col < kw) ? g_h2[(rb + (i >> 5)) * 9344 + kc + k0 + col] : 0.f;
        }
        for (int i = tid; i < 2048; i += 256) {
            int col = i & 31;
            sB[i >> 5][col] = (col < kw) ? W[(i >> 5) * 9344 + kc + k0 + col] : 0.f;
        }
        __syncthreads();
        #pragma unroll
        for (int kk = 0; kk < 32; kk++) {
            float a = sA[r][kk];
            a0 += a * sB[cg * 4 + 0][kk];
            a1 += a * sB[cg * 4 + 1][kk];
            a2 += a * sB[cg * 4 + 2][kk];
            a3 += a * sB[cg * 4 + 3][kk];
        }
        __syncthreads();
    }
    float* yp = g_ypart + blockIdx.y * 32768 + (rb + r) * 64 + cg * 4;
    yp[0] = a0; yp[1] = a1; yp[2] = a2; yp[3] = a3;
}

__global__ void k_yred(const float* __restrict__ bias) {
    int i = blockIdx.x * 256 + threadIdx.x;
    float acc = bias[i & 63];
    #pragma unroll
    for (int s = 0; s < 16; s++) acc += g_ypart[s * 32768 + i];
    g_y[i] = acc;
}

// K5: patch embed + cls + pos
__global__ void k_patch(const float* __restrict__ pw, const float* __restrict__ pb,
                        const float* __restrict__ cls, const float* __restrict__ pos) {
    __shared__ float s_x[7500], s_w[1600];
    int b = blockIdx.x, tid = threadIdx.x;
    const float* xs = g_xs + b * 7500;
    for (int i = tid; i < 7500; i += 256) s_x[i] = xs[i];
    for (int i = tid; i < 1600; i += 256) s_w[i] = pw[i];
    __syncthreads();
    float* xo = g_x + b * 301 * 64;
    if (tid < 64) xo[tid] = cls[tid] + pos[tid];
    for (int idx = tid; idx < 19200; idx += 256) {
        int t = idx >> 6, o = idx & 63;
        const float* xr = s_x + t * 25;
        const float* wr = s_w + o * 25;
        float acc = pb[o] + pos[(t + 1) * 64 + o];
        #pragma unroll
        for (int p = 0; p < 25; p++) acc += xr[p] * wr[p];
        xo[(t + 1) * 64 + o] = acc;
    }
}

// K6: LN1 + QKV (64->192), 256 threads, 4x6 blocking
__global__ void __launch_bounds__(256) k_qkv(int l, const float* __restrict__ lg,
                      const float* __restrict__ lb, const float* __restrict__ w) {
    extern __shared__ float sm[];
    float* s_w  = sm;            // 192 rows * 66
    float* s_xn = sm + 12672;    // 32 rows * 66
    int b = blockIdx.x, tbase = blockIdx.y * 32, tid = threadIdx.x;
    int warp = tid >> 5, lane = tid & 31;
    for (int i = tid; i < 12288; i += 256)
        s_w[(i >> 6) * 66 + (i & 63)] = w[l * 12288 + i];
    if (warp < 8) {
        #pragma unroll
        for (int tt = 0; tt < 4; tt++) {
            int t = warp * 4 + tt, tg = tbase + t;
            float2 v = make_float2(0.f, 0.f);
            if (tg < 301) v = *(const float2*)(g_x + (b * 301 + tg) * 64 + lane * 2);
            float s = v.x + v.y;
            #pragma unroll
            for (int o = 16; o; o >>= 1) s += __shfl_xor_sync(0xffffffffu, s, o);
            float m = s * (1.f / 64.f);
            float d0 = v.x - m, d1 = v.y - m;
            float sq = d0 * d0 + d1 * d1;
            #pragma unroll
            for (int o = 16; o; o >>= 1) sq += __shfl_xor_sync(0xffffffffu, sq, o);
            float rstd = rsqrtf(sq * (1.f / 64.f) + 1e-5f);
            s_xn[t * 66 + lane * 2]     = d0 * rstd * lg[l * 64 + lane * 2]     + lb[l * 64 + lane * 2];
            s_xn[t * 66 + lane * 2 + 1] = d1 * rstd * lg[l * 64 + lane * 2 + 1] + lb[l * 64 + lane * 2 + 1];
        }
    }
    __syncthreads();
    int t0 = tid & 7, j0 = (tid >> 3) * 6;
    float2 acc[4][6];
    #pragma unroll
    for (int m = 0; m < 4; m++)
    #pragma unroll
    for (int n = 0; n < 6; n++) acc[m][n] = make_float2(0.f, 0.f);
    const float2* x2 = (const float2*)s_xn;
    const float2* w2 = (const float2*)s_w;
    #pragma unroll 4
    for (int k = 0; k < 32; k++) {
        float2 xv[4], wv[6];
        #pragma unroll
        for (int m = 0; m < 4; m++) xv[m] = x2[(t0 + 8 * m) * 33 + k];
        #pragma unroll
        for (int n = 0; n < 6; n++) wv[n] = w2[(j0 + n) * 33 + k];
        #pragma unroll
        for (int m = 0; m < 4; m++)
        #pragma unroll
        for (int n = 0; n < 6; n++) acc[m][n] = ffma2(xv[m], wv[n], acc[m][n]);
    }
    #pragma unroll
    for (int m = 0; m < 4; m++) {
        int tg = tbase + t0 + 8 * m;
        if (tg < 301) {
            float* op = g_qkv + (b * 301 + tg) * 192 + j0;
            #pragma unroll
            for (int n = 0; n < 3; n++) {
                float2 r = make_float2(acc[m][2 * n].x + acc[m][2 * n].y,
                                       acc[m][2 * n + 1].x + acc[m][2 * n + 1].y);
                *(float2*)(op + 2 * n) = r;
            }
        }
    }
}

// K7: tensor-core flash attention per (b, head), mma.sync m16n8k16 bf16.
// Warp owns 16 q-rows; loops over 19 j-chunks of 16; S-frag -> exp -> A-frag of PV.
__global__ void __launch_bounds__(320) k_attn() {
    __shared__ __nv_bfloat16 sQ[304 * 16];     // [row][d], Q pre-scaled by 0.25
    __shared__ __nv_bfloat16 sK[304 * 16];     // [row][d]
    __shared__ __nv_bfloat16 sVt[16 * 312];    // [d][j], stride 312 (conflict-free)
    int b = blockIdx.x, h = blockIdx.y, tid = threadIdx.x;
    const float* qkv = g_qkv + b * 301 * 192;
    for (int i = tid; i < 304 * 4; i += 320) {
        int j = i >> 2, dq = (i & 3) * 4;
        float4 qv = make_float4(0.f, 0.f, 0.f, 0.f), kv = qv, vv = qv;
        if (j < 301) {
            const float* base = qkv + j * 192 + h * 16 + dq;
            qv = *(const float4*)(base);
            kv = *(const float4*)(base + 64);
            vv = *(const float4*)(base + 128);
        }
        *(unsigned*)&sQ[j * 16 + dq]     = packbf(qv.x * 0.25f, qv.y * 0.25f);
        *(unsigned*)&sQ[j * 16 + dq + 2] = packbf(qv.z * 0.25f, qv.w * 0.25f);
        *(unsigned*)&sK[j * 16 + dq]     = packbf(kv.x, kv.y);
        *(unsigned*)&sK[j * 16 + dq + 2] = packbf(kv.z, kv.w);
        sVt[(dq + 0) * 312 + j] = __float2bfloat16(vv.x);
        sVt[(dq + 1) * 312 + j] = __float2bfloat16(vv.y);
        sVt[(dq + 2) * 312 + j] = __float2bfloat16(vv.z);
        sVt[(dq + 3) * 312 + j] = __float2bfloat16(vv.w);
    }
    __syncthreads();
    int warp = tid >> 5, l = tid & 31;
    int lq = l >> 2, lr = l & 3;                 // quad-id, in-quad lane
    for (int qc = warp; qc < 19; qc += 10) {
        int base = qc * 16;
        unsigned a[4];
        a[0] = *(const unsigned*)&sQ[(base + lq) * 16 + lr * 2];
        a[1] = *(const unsigned*)&sQ[(base + 8 + lq) * 16 + lr * 2];
        a[2] = *(const unsigned*)&sQ[(base + lq) * 16 + lr * 2 + 8];
        a[3] = *(const unsigned*)&sQ[(base + 8 + lq) * 16 + lr * 2 + 8];
        float o0[4] = {0.f, 0.f, 0.f, 0.f}, o1[4] = {0.f, 0.f, 0.f, 0.f};
        float rs0 = 0.f, rs1 = 0.f;
        const float zc[4] = {0.f, 0.f, 0.f, 0.f};
        for (int cc = 0; cc < 19; cc++) {
            int jb0 = cc * 16, jb1 = jb0 + 8;
            unsigned bk0[2], bk1[2];
            bk0[0] = *(const unsigned*)&sK[(jb0 + lq) * 16 + lr * 2];
            bk0[1] = *(const unsigned*)&sK[(jb0 + lq) * 16 + lr * 2 + 8];
            bk1[0] = *(const unsigned*)&sK[(jb1 + lq) * 16 + lr * 2];
            bk1[1] = *(const unsigned*)&sK[(jb1 + lq) * 16 + lr * 2 + 8];
            float s0[4], s1[4];
            mma16816(s0, a, bk0, zc);
            mma16816(s1, a, bk1, zc);
            int c00 = jb0 + lr * 2, c10 = jb1 + lr * 2;
            float p00 = (c00 < 301)     ? __expf(s0[0]) : 0.f;
            float p01 = (c00 + 1 < 301) ? __expf(s0[1]) : 0.f;
            float p02 = (c00 < 301)     ? __expf(s0[2]) : 0.f;
            float p03 = (c00 + 1 < 301) ? __expf(s0[3]) : 0.f;
            float p10 = (c10 < 301)     ? __expf(s1[0]) : 0.f;
            float p11 = (c10 + 1 < 301) ? __expf(s1[1]) : 0.f;
            float p12 = (c10 < 301)     ? __expf(s1[2]) : 0.f;
            float p13 = (c10 + 1 < 301) ? __expf(s1[3]) : 0.f;
            rs0 += (p00 + p01) + (p10 + p11);
            rs1 += (p02 + p03) + (p12 + p13);
            unsigned pa[4];
            pa[0] = packbf(p00, p01);
            pa[1] = packbf(p02, p03);
            pa[2] = packbf(p10, p11);
            pa[3] = packbf(p12, p13);
            unsigned bv0[2], bv1[2];
            int jj = jb0 + lr * 2;
            bv0[0] = *(const unsigned*)&sVt[lq * 312 + jj];
            bv0[1] = *(const unsigned*)&sVt[lq * 312 + jj + 8];
            bv1[0] = *(const unsigned*)&sVt[(lq + 8) * 312 + jj];
            bv1[1] = *(const unsigned*)&sVt[(lq + 8) * 312 + jj + 8];
            mma16816(o0, pa, bv0, o0);
            mma16816(o1, pa, bv1, o1);
        }
        rs0 += __shfl_xor_sync(0xffffffffu, rs0, 1);
        rs0 += __shfl_xor_sync(0xffffffffu, rs0, 2);
        rs1 += __shfl_xor_sync(0xffffffffu, rs1, 1);
        rs1 += __shfl_xor_sync(0xffffffffu, rs1, 2);
        float inv0 = 1.f / rs0, inv1 = 1.f / rs1;
        int row0 = base + lq, row1 = row0 + 8;
        if (row0 < 301) {
            float* op = g_o + (b * 301 + row0) * 64 + h * 16 + lr * 2;
            *(float2*)op       = make_float2(o0[0] * inv0, o0[1] * inv0);
            *(float2*)(op + 8) = make_float2(o1[0] * inv0, o1[1] * inv0);
        }
        if (row1 < 301) {
            float* op = g_o + (b * 301 + row1) * 64 + h * 16 + lr * 2;
            *(float2*)op       = make_float2(o0[2] * inv1, o0[3] * inv1);
            *(float2*)(op + 8) = make_float2(o1[2] * inv1, o1[3] * inv1);
        }
    }
}

// K8: out projection + residual, 128 threads, 4x4 blocking
__global__ void __launch_bounds__(128) k_proj(int l, const float* __restrict__ W,
                                              const float* __restrict__ B) {
    __shared__ float s_w[64 * 66], s_o[32 * 66];
    int b = blockIdx.x, tbase = blockIdx.y * 32, tid = threadIdx.x;
    for (int i = tid; i < 4096; i += 128) {
        int j = i >> 6, k = i & 63;
        s_w[j * 66 + k] = W[l * 4096 + i];
    }
    for (int i = tid; i < 2048; i += 128) {
        int t = i >> 6, k = i & 63, tg = tbase + t;
        s_o[t * 66 + k] = (tg < 301) ? g_o[(b * 301 + tg) * 64 + k] : 0.f;
    }
    __syncthreads();
    int t0 = tid & 7, j0 = (tid >> 3) * 4;
    float2 acc[4][4];
    #pragma unroll
    for (int m = 0; m < 4; m++)
    #pragma unroll
    for (int n = 0; n < 4; n++) acc[m][n] = make_float2(0.f, 0.f);
    const float2* x2 = (const float2*)s_o;
    const float2* w2 = (const float2*)s_w;
    #pragma unroll 4
    for (int k = 0; k < 32; k++) {
        float2 xv[4], wv[4];
        #pragma unroll
        for (int m = 0; m < 4; m++) xv[m] = x2[(t0 + 8 * m) * 33 + k];
        #pragma unroll
        for (int n = 0; n < 4; n++) wv[n] = w2[(j0 + n) * 33 + k];
        #pragma unroll
        for (int m = 0; m < 4; m++)
        #pragma unroll
        for (int n = 0; n < 4; n++) acc[m][n] = ffma2(xv[m], wv[n], acc[m][n]);
    }
    float4 bb = *(const float4*)(B + l * 64 + j0);
    #pragma unroll
    for (int m = 0; m < 4; m++) {
        int tg = tbase + t0 + 8 * m;
        if (tg < 301) {
            float4* xp = (float4*)(g_x + (b * 301 + tg) * 64 + j0);
            float4 v = *xp;
            v.x += acc[m][0].x + acc[m][0].y + bb.x;
            v.y += acc[m][1].x + acc[m][1].y + bb.y;
            v.z += acc[m][2].x + acc[m][2].y + bb.z;
            v.w += acc[m][3].x + acc[m][3].y + bb.w;
            *xp = v;
        }
    }
}

// K9: LN2 + MLP + residual
__global__ void k_ff(int l, const float* __restrict__ lg, const float* __restrict__ lb,
                     const float* __restrict__ w1, const float* __restrict__ b1,
                     const float* __restrict__ w2, const float* __restrict__ b2) {
    __shared__ float s_w1[512], s_w2[512], s_b1[8], s_b2[64], s_g[64], s_bb[64];
    int tid = threadIdx.x;
    for (int i = tid; i < 512; i += 256) { s_w1[i] = w1[l * 512 + i]; s_w2[i] = w2[l * 512 + i]; }
    if (tid < 8)  s_b1[tid] = b1[l * 8 + tid];
    if (tid < 64) { s_b2[tid] = b2[l * 64 + tid]; s_g[tid] = lg[l * 64 + tid]; s_bb[tid] = lb[l * 64 + tid]; }
    __syncthreads();
    int gid = blockIdx.x * 256 + tid;
    float* xr = g_x + gid * 64;
    float xv[64];
    float4* x4 = (float4*)xr;
    #pragma unroll
    for (int i = 0; i < 16; i++) {
        float4 v = x4[i];
        xv[4 * i] = v.x; xv[4 * i + 1] = v.y; xv[4 * i + 2] = v.z; xv[4 * i + 3] = v.w;
    }
    float s = 0.f;
    #pragma unroll
    for (int k = 0; k < 64; k++) s += xv[k];
    float m = s * (1.f / 64.f), sq = 0.f;
    #pragma unroll
    for (int k = 0; k < 64; k++) { float d = xv[k] - m; sq += d * d; }
    float rstd = rsqrtf(sq * (1.f / 64.f) + 1e-5f);
    float hid[8];
    #pragma unroll
    for (int mm = 0; mm < 8; mm++) hid[mm] = s_b1[mm];
    #pragma unroll
    for (int k = 0; k < 64; k++) {
        float xn = (xv[k] - m) * rstd * s_g[k] + s_bb[k];
        #pragma unroll
        for (int mm = 0; mm < 8; mm++) hid[mm] += xn * s_w1[mm * 64 + k];
    }
    #pragma unroll
    for (int mm = 0; mm < 8; mm++) {
        float hv = hid[mm];
        hid[mm] = 0.5f * hv * (1.f + erff(hv * 0.70710678118654752f));
    }
    #pragma unroll
    for (int k = 0; k < 64; k++) {
        float acc = s_b2[k];
        #pragma unroll
        for (int mm = 0; mm < 8; mm++) acc += hid[mm] * s_w2[k * 8 + mm];
        xv[k] += acc;
    }
    #pragma unroll
    for (int i = 0; i < 16; i++)
        x4[i] = make_float4(xv[4 * i], xv[4 * i + 1], xv[4 * i + 2], xv[4 * i + 3]);
}

// K10: head
__global__ void k_head(const float* __restrict__ hg, const float* __restrict__ hb,
                       const float* __restrict__ W, const float* __restrict__ B,
                       float* __restrict__ out) {
    __shared__ float s_z[128], s_red[8];
    int b = blockIdx.x, tid = threadIdx.x;
    int warp = tid >> 5, lane = tid & 31;
    float z = (tid < 64) ? g_x[b * 301 * 64 + tid] : g_y[b * 64 + tid - 64];
    float s = z;
    #pragma unroll
    for (int o = 16; o; o >>= 1) s += __shfl_xor_sync(0xffffffffu, s, o);
    if (lane == 0) s_red[warp] = s;
    __syncthreads();
    float m = (s_red[0] + s_red[1] + s_red[2] + s_red[3]) * (1.f / 128.f);
    float d = z - m, sq = d * d;
    #pragma unroll
    for (int o = 16; o; o >>= 1) sq += __shfl_xor_sync(0xffffffffu, sq, o);
    if (lane == 0) s_red[4 + warp] = sq;
    __syncthreads();
    float var = (s_red[4] + s_red[5] + s_red[6] + s_red[7]) * (1.f / 128.f);
    float rstd = rsqrtf(var + 1e-5f);
    s_z[tid] = d * rstd * hg[tid] + hb[tid];
    __syncthreads();
    if (tid < 16) {
        float acc = B[tid];
        const float* wr = W + tid * 128;
        #pragma unroll 16
        for (int k = 0; k < 128; k++) acc += s_z[k] * wr[k];
        out[b * 16 + tid] = acc;
    }
}

extern "C" void kernel_launch(void* const* d_in, const int* in_sizes, int n_in,
                              void* d_out, int out_size) {
    const float* input   = (const float*)d_in[0];
    const float* sse_w   = (const float*)d_in[1];
    const float* sse_b   = (const float*)d_in[2];
    const float* conv1_w = (const float*)d_in[3];
    const float* conv1_b = (const float*)d_in[4];
    const float* conv2_w = (const float*)d_in[5];
    const float* conv2_b = (const float*)d_in[6];
    const float* dense1_w= (const float*)d_in[7];
    const float* dense1_b= (const float*)d_in[8];
    const float* patch_w = (const float*)d_in[9];
    const float* patch_b = (const float*)d_in[10];
    const float* cls_tok = (const float*)d_in[11];
    const float* pos_emb = (const float*)d_in[12];
    const float* ln1_g   = (const float*)d_in[13];
    const float* ln1_b   = (const float*)d_in[14];
    const float* qkv_w   = (const float*)d_in[15];
    const float* ao_w    = (const float*)d_in[16];
    const float* ao_b    = (const float*)d_in[17];
    const float* ln2_g   = (const float*)d_in[18];
    const float* ln2_b   = (const float*)d_in[19];
    const float* ff1_w   = (const float*)d_in[20];
    const float* ff1_b   = (const float*)d_in[21];
    const float* ff2_w   = (const float*)d_in[22];
    const float* ff2_b   = (const float*)d_in[23];
    const float* hln_g   = (const float*)d_in[24];
    const float* hln_b   = (const float*)d_in[25];
    const float* head_w  = (const float*)d_in[26];
    const float* head_b  = (const float*)d_in[27];
    float* out = (float*)d_out;

    static bool attr_done = false;
    if (!attr_done) {
        cudaFuncSetAttribute(k_conv2, cudaFuncAttributeMaxDynamicSharedMemorySize, 99200);
        cudaFuncSetAttribute(k_qkv,   cudaFuncAttributeMaxDynamicSharedMemorySize, 59136);
        attr_done = true;
    }

    k_sse<<<512, 256>>>(input, sse_w, sse_b);                            // #1
    k_patch<<<512, 256>>>(patch_w, patch_b, cls_tok, pos_emb);           // #2
    for (int l = 0; l < 5; l++) {
        k_qkv<<<dim3(512, 10), 256, 59136>>>(l, ln1_g, ln1_b, qkv_w);    // #3 (l=0)
        k_attn<<<dim3(512, 4), 320>>>();                                 // #4 (l=0) -> profiled
        k_proj<<<dim3(512, 10), 128>>>(l, ao_w, ao_b);
        k_ff<<<602, 256>>>(l, ln2_g, ln2_b, ff1_w, ff1_b, ff2_w, ff2_b);
    }
    k_conv1<<<512, 256>>>(conv1_w, conv1_b);
    k_conv2<<<dim3(512, 4), 256, 99200>>>(conv2_w, conv2_b);
    k_dense1<<<dim3(32, 16), 256>>>(dense1_w);
    k_yred<<<128, 256>>>(dense1_b);
    k_head<<<512, 128>>>(hln_g, hln_b, head_w, head_b, out);
}

// round 15
// speedup vs baseline: 2.2161x; 1.2361x over previous
#include <cuda_runtime.h>
#include <cuda_bf16.h>
#include <cstring>
#include <math.h>

static __device__ float g_xs[512 * 7500];
static __device__ float g_h1[512 * 42336];
static __device__ float g_h2[512 * 9344];
static __device__ float g_ypart[16 * 512 * 64];
static __device__ float g_y[512 * 64];
static __device__ float g_x[512 * 301 * 64];
static __device__ float g_qkv[512 * 301 * 192];   // token-major [b][301][192]
static __device__ float g_o[512 * 301 * 64];

__device__ __forceinline__ float2 ffma2(float2 a, float2 b, float2 c) {
    unsigned long long ua, ub, uc, ud;
    memcpy(&ua, &a, 8); memcpy(&ub, &b, 8); memcpy(&uc, &c, 8);
    asm("fma.rn.f32x2 %0, %1, %2, %3;" : "=l"(ud) : "l"(ua), "l"(ub), "l"(uc));
    float2 d; memcpy(&d, &ud, 8);
    return d;
}

__device__ __forceinline__ unsigned packbf(float x, float y) {
    __nv_bfloat162 t = __floats2bfloat162_rn(x, y);
    unsigned u; memcpy(&u, &t, 4);
    return u;
}

__device__ __forceinline__ void mma16816(float* d, const unsigned* a,
                                         const unsigned* b, const float* c) {
    asm volatile(
        "mma.sync.aligned.m16n8k16.row.col.f32.bf16.bf16.f32 "
        "{%0,%1,%2,%3}, {%4,%5,%6,%7}, {%8,%9}, {%10,%11,%12,%13};"
        : "=f"(d[0]), "=f"(d[1]), "=f"(d[2]), "=f"(d[3])
        : "r"(a[0]), "r"(a[1]), "r"(a[2]), "r"(a[3]),
          "r"(b[0]), "r"(b[1]),
          "f"(c[0]), "f"(c[1]), "f"(c[2]), "f"(c[3]));
}

// K1: SSE gate
__global__ void k_sse(const float* __restrict__ in, const float* __restrict__ sw,
                      const float* __restrict__ sb) {
    int b = blockIdx.x, tid = threadIdx.x;
    __shared__ float s_w[300], s_g[25];
    const float* x = in + b * 7500;
    for (int i = tid; i < 300; i += 256) s_w[i] = sw[i];
    __syncthreads();
    int warp = tid >> 5, lane = tid & 31;
    for (int p = warp; p < 25; p += 8) {
        float acc = 0.f;
        const float* xp = x + p * 300;
        for (int c = lane; c < 300; c += 32) acc += xp[c] * s_w[c];
        #pragma unroll
        for (int o = 16; o; o >>= 1) acc += __shfl_xor_sync(0xffffffffu, acc, o);
        if (lane == 0) s_g[p] = 1.f / (1.f + expf(-(acc + sb[0])));
    }
    __syncthreads();
    float* xo = g_xs + b * 7500;
    for (int i = tid; i < 7500; i += 256) xo[i] = x[i] * s_g[i / 300];
}

// K2: conv1 (1->16, 3x3x7) + relu
__global__ void k_conv1(const float* __restrict__ W, const float* __restrict__ B) {
    int b = blockIdx.x, tid = threadIdx.x;
    __shared__ float sx[7552], sw[1008], sb[16];
    const float* xs = g_xs + b * 7500;
    for (int i = tid; i < 7552; i += 256) sx[i] = (i < 7500) ? xs[i] : 0.f;
    for (int i = tid; i < 1008; i += 256) sw[i] = W[i];
    if (tid < 16) sb[tid] = B[tid];
    __syncthreads();
    float* out = g_h1 + b * 42336;
    int warp = tid >> 5, lane = tid & 31, w0 = lane * 10;
    for (int row = warp; row < 144; row += 8) {
        int o = row / 9, dh = row % 9, d = dh / 3, hh = dh % 3;
        const float* wp = sw + o * 63;
        float acc[10];
        #pragma unroll
        for (int u = 0; u < 10; u++) acc[u] = sb[o];
        #pragma unroll
        for (int kd = 0; kd < 3; kd++)
        #pragma unroll
        for (int kh = 0; kh < 3; kh++) {
            const float* ip = sx + (d + kd) * 1500 + (hh + kh) * 300 + w0;
            float iv[16];
            #pragma unroll
            for (int u = 0; u < 16; u++) iv[u] = ip[u];
            const float* wq = wp + kd * 21 + kh * 7;
            #pragma unroll
            for (int kw = 0; kw < 7; kw++) {
                float wv = wq[kw];
                #pragma unroll
                for (int u = 0; u < 10; u++) acc[u] += iv[u + kw] * wv;
            }
        }
        #pragma unroll
        for (int u = 0; u < 10; u++)
            if (w0 + u < 294) out[row * 294 + w0 + u] = fmaxf(acc[u], 0.f);
    }
}

// K3: conv2 (16->32, 3x3x3) + relu, W-tiled grid (512, 4)
__global__ void k_conv2(const float* __restrict__ W, const float* __restrict__ B) {
    extern __shared__ float sm[];
    float* s_in = sm;             // 144 * 76 = 10944
    float* s_w  = sm + 10944;     // 32 * 433 = 13856
    int b = blockIdx.x, w0 = blockIdx.y * 73, tid = threadIdx.x;
    const float* hin = g_h1 + b * 42336;
    for (int i = tid; i < 10944; i += 256) {
        int row = i / 76, c = i % 76;
        s_in[i] = (w0 + c < 294) ? hin[row * 294 + w0 + c] : 0.f;
    }
    for (int i = tid; i < 13824; i += 256)
        s_w[(i / 432) * 433 + (i % 432)] = W[i];
    __syncthreads();
    float* out = g_h2 + b * 9344;
    for (int t = tid; t < 608; t += 256) {
        int oc = t & 31, wl = (t >> 5) * 4;
        const float* wp = s_w + oc * 433;
        float a0 = 0.f, a1 = 0.f, a2 = 0.f, a3 = 0.f;
        for (int ic = 0; ic < 16; ic++)
        #pragma unroll
        for (int kd = 0; kd < 3; kd++)
        #pragma unroll
        for (int kh = 0; kh < 3; kh++) {
            const float* ip = s_in + (ic * 9 + kd * 3 + kh) * 76 + wl;
            float i0 = ip[0], i1 = ip[1], i2 = ip[2];
            float i3 = ip[3], i4 = ip[4], i5 = ip[5];
            const float* wq = wp + (ic * 9 + kd * 3 + kh) * 3;
            float v0 = wq[0], v1 = wq[1], v2 = wq[2];
            a0 += i0 * v0 + i1 * v1 + i2 * v2;
            a1 += i1 * v0 + i2 * v1 + i3 * v2;
            a2 += i2 * v0 + i3 * v1 + i4 * v2;
            a3 += i3 * v0 + i4 * v1 + i5 * v2;
        }
        float bb = B[oc];
        float r[4] = {a0, a1, a2, a3};
        #pragma unroll
        for (int u = 0; u < 4; u++)
            if (wl + u < 73) out[oc * 292 + w0 + wl + u] = fmaxf(r[u] + bb, 0.f);
    }
}

// K4: dense1 (9344->64), split-K 16
__global__ void k_dense1(const float* __restrict__ W) {
    __shared__ float sA[16][33], sB[64][33];
    int rb = blockIdx.x * 16, kc = blockIdx.y * 584, tid = threadIdx.x;
    int r = tid & 15, cg = tid >> 4;
    float a0 = 0.f, a1 = 0.f, a2 = 0.f, a3 = 0.f;
    for (int k0 = 0; k0 < 584; k0 += 32) {
        int kw = 584 - k0 < 32 ? 584 - k0 : 32;
        for (int i = tid; i < 512; i += 256) {
            int col = i & 31;
            sA[i >> 5][col] = (col < kw) ? g_h2[(rb + (i >> 5)) * 9344 + kc + k0 + col] : 0.f;
        }
        for (int i = tid; i < 2048; i += 256) {
            int col = i & 31;
            sB[i >> 5][col] = (col < kw) ? W[(i >> 5) * 9344 + kc + k0 + col] : 0.f;
        }
        __syncthreads();
        #pragma unroll
        for (int kk = 0; kk < 32; kk++) {
            float a = sA[r][kk];
            a0 += a * sB[cg * 4 + 0][kk];
            a1 += a * sB[cg * 4 + 1][kk];
            a2 += a * sB[cg * 4 + 2][kk];
            a3 += a * sB[cg * 4 + 3][kk];
        }
        __syncthreads();
    }
    float* yp = g_ypart + blockIdx.y * 32768 + (rb + r) * 64 + cg * 4;
    yp[0] = a0; yp[1] = a1; yp[2] = a2; yp[3] = a3;
}

__global__ void k_yred(const float* __restrict__ bias) {
    int i = blockIdx.x * 256 + threadIdx.x;
    float acc = bias[i & 63];
    #pragma unroll
    for (int s = 0; s < 16; s++) acc += g_ypart[s * 32768 + i];
    g_y[i] = acc;
}

// K5: patch embed + cls + pos
__global__ void k_patch(const float* __restrict__ pw, const float* __restrict__ pb,
                        const float* __restrict__ cls, const float* __restrict__ pos) {
    __shared__ float s_x[7500], s_w[1600];
    int b = blockIdx.x, tid = threadIdx.x;
    const float* xs = g_xs + b * 7500;
    for (int i = tid; i < 7500; i += 256) s_x[i] = xs[i];
    for (int i = tid; i < 1600; i += 256) s_w[i] = pw[i];
    __syncthreads();
    float* xo = g_x + b * 301 * 64;
    if (tid < 64) xo[tid] = cls[tid] + pos[tid];
    for (int idx = tid; idx < 19200; idx += 256) {
        int t = idx >> 6, o = idx & 63;
        const float* xr = s_x + t * 25;
        const float* wr = s_w + o * 25;
        float acc = pb[o] + pos[(t + 1) * 64 + o];
        #pragma unroll
        for (int p = 0; p < 25; p++) acc += xr[p] * wr[p];
        xo[(t + 1) * 64 + o] = acc;
    }
}

// K6: LN1 + QKV (64->192) via mma.sync bf16, 64 tokens/block, grid (512, 5)
__global__ void __launch_bounds__(512) k_qkv(int l, const float* __restrict__ lg,
                      const float* __restrict__ lb, const float* __restrict__ w) {
    __shared__ __nv_bfloat16 s_w[192 * 68];    // [j][k], stride 68
    __shared__ __nv_bfloat16 s_xn[64 * 68];    // [t][k], stride 68
    int b = blockIdx.x, tbase = blockIdx.y * 64, tid = threadIdx.x;
    int warp = tid >> 5, lane = tid & 31;
    for (int i = tid; i < 12288; i += 512)
        s_w[(i >> 6) * 68 + (i & 63)] = __float2bfloat16(w[l * 12288 + i]);
    // LN: 16 warps x 4 tokens = 64 tokens
    #pragma unroll
    for (int tt = 0; tt < 4; tt++) {
        int t = warp * 4 + tt, tg = tbase + t;
        float2 v = make_float2(0.f, 0.f);
        if (tg < 301) v = *(const float2*)(g_x + (b * 301 + tg) * 64 + lane * 2);
        float s = v.x + v.y;
        #pragma unroll
        for (int o = 16; o; o >>= 1) s += __shfl_xor_sync(0xffffffffu, s, o);
        float m = s * (1.f / 64.f);
        float d0 = v.x - m, d1 = v.y - m;
        float sq = d0 * d0 + d1 * d1;
        #pragma unroll
        for (int o = 16; o; o >>= 1) sq += __shfl_xor_sync(0xffffffffu, sq, o);
        float rstd = rsqrtf(sq * (1.f / 64.f) + 1e-5f);
        float xn0 = d0 * rstd * lg[l * 64 + lane * 2]     + lb[l * 64 + lane * 2];
        float xn1 = d1 * rstd * lg[l * 64 + lane * 2 + 1] + lb[l * 64 + lane * 2 + 1];
        *(unsigned*)&s_xn[t * 68 + lane * 2] = packbf(xn0, xn1);
    }
    __syncthreads();
    // mma: warp = (m-tile 0..3, n-chunk 0..3 of 48 cols)
    int m = warp & 3, nc = warp >> 2;
    int lq = lane >> 2, lr = lane & 3;
    unsigned a[4][4];
    #pragma unroll
    for (int kk = 0; kk < 4; kk++) {
        int kof = kk * 16;
        a[kk][0] = *(const unsigned*)&s_xn[(m * 16 + lq) * 68 + kof + lr * 2];
        a[kk][1] = *(const unsigned*)&s_xn[(m * 16 + 8 + lq) * 68 + kof + lr * 2];
        a[kk][2] = *(const unsigned*)&s_xn[(m * 16 + lq) * 68 + kof + lr * 2 + 8];
        a[kk][3] = *(const unsigned*)&s_xn[(m * 16 + 8 + lq) * 68 + kof + lr * 2 + 8];
    }
    int tg0 = tbase + m * 16 + lq, tg1 = tg0 + 8;
    #pragma unroll
    for (int n8 = 0; n8 < 6; n8++) {
        int col0 = nc * 48 + n8 * 8;
        float dacc[4] = {0.f, 0.f, 0.f, 0.f};
        #pragma unroll
        for (int kk = 0; kk < 4; kk++) {
            unsigned bf[2];
            bf[0] = *(const unsigned*)&s_w[(col0 + lq) * 68 + kk * 16 + lr * 2];
            bf[1] = *(const unsigned*)&s_w[(col0 + lq) * 68 + kk * 16 + lr * 2 + 8];
            mma16816(dacc, a[kk], bf, dacc);
        }
        if (tg0 < 301)
            *(float2*)(g_qkv + (b * 301 + tg0) * 192 + col0 + lr * 2) = make_float2(dacc[0], dacc[1]);
        if (tg1 < 301)
            *(float2*)(g_qkv + (b * 301 + tg1) * 192 + col0 + lr * 2) = make_float2(dacc[2], dacc[3]);
    }
}

// K7: tensor-core flash attention per (b, head), mma.sync m16n8k16 bf16
__global__ void __launch_bounds__(320) k_attn() {
    __shared__ __nv_bfloat16 sQ[304 * 16];
    __shared__ __nv_bfloat16 sK[304 * 16];
    __shared__ __nv_bfloat16 sVt[16 * 312];
    int b = blockIdx.x, h = blockIdx.y, tid = threadIdx.x;
    const float* qkv = g_qkv + b * 301 * 192;
    for (int i = tid; i < 304 * 4; i += 320) {
        int j = i >> 2, dq = (i & 3) * 4;
        float4 qv = make_float4(0.f, 0.f, 0.f, 0.f), kv = qv, vv = qv;
        if (j < 301) {
            const float* base = qkv + j * 192 + h * 16 + dq;
            qv = *(const float4*)(base);
            kv = *(const float4*)(base + 64);
            vv = *(const float4*)(base + 128);
        }
        *(unsigned*)&sQ[j * 16 + dq]     = packbf(qv.x * 0.25f, qv.y * 0.25f);
        *(unsigned*)&sQ[j * 16 + dq + 2] = packbf(qv.z * 0.25f, qv.w * 0.25f);
        *(unsigned*)&sK[j * 16 + dq]     = packbf(kv.x, kv.y);
        *(unsigned*)&sK[j * 16 + dq + 2] = packbf(kv.z, kv.w);
        sVt[(dq + 0) * 312 + j] = __float2bfloat16(vv.x);
        sVt[(dq + 1) * 312 + j] = __float2bfloat16(vv.y);
        sVt[(dq + 2) * 312 + j] = __float2bfloat16(vv.z);
        sVt[(dq + 3) * 312 + j] = __float2bfloat16(vv.w);
    }
    __syncthreads();
    int warp = tid >> 5, l = tid & 31;
    int lq = l >> 2, lr = l & 3;
    for (int qc = warp; qc < 19; qc += 10) {
        int base = qc * 16;
        unsigned a[4];
        a[0] = *(const unsigned*)&sQ[(base + lq) * 16 + lr * 2];
        a[1] = *(const unsigned*)&sQ[(base + 8 + lq) * 16 + lr * 2];
        a[2] = *(const unsigned*)&sQ[(base + lq) * 16 + lr * 2 + 8];
        a[3] = *(const unsigned*)&sQ[(base + 8 + lq) * 16 + lr * 2 + 8];
        float o0[4] = {0.f, 0.f, 0.f, 0.f}, o1[4] = {0.f, 0.f, 0.f, 0.f};
        float rs0 = 0.f, rs1 = 0.f;
        const float zc[4] = {0.f, 0.f, 0.f, 0.f};
        for (int cc = 0; cc < 19; cc++) {
            int jb0 = cc * 16, jb1 = jb0 + 8;
            unsigned bk0[2], bk1[2];
            bk0[0] = *(const unsigned*)&sK[(jb0 + lq) * 16 + lr * 2];
            bk0[1] = *(const unsigned*)&sK[(jb0 + lq) * 16 + lr * 2 + 8];
            bk1[0] = *(const unsigned*)&sK[(jb1 + lq) * 16 + lr * 2];
            bk1[1] = *(const unsigned*)&sK[(jb1 + lq) * 16 + lr * 2 + 8];
            float s0[4], s1[4];
            mma16816(s0, a, bk0, zc);
            mma16816(s1, a, bk1, zc);
            int c00 = jb0 + lr * 2, c10 = jb1 + lr * 2;
            float p00 = (c00 < 301)     ? __expf(s0[0]) : 0.f;
            float p01 = (c00 + 1 < 301) ? __expf(s0[1]) : 0.f;
            float p02 = (c00 < 301)     ? __expf(s0[2]) : 0.f;
            float p03 = (c00 + 1 < 301) ? __expf(s0[3]) : 0.f;
            float p10 = (c10 < 301)     ? __expf(s1[0]) : 0.f;
            float p11 = (c10 + 1 < 301) ? __expf(s1[1]) : 0.f;
            float p12 = (c10 < 301)     ? __expf(s1[2]) : 0.f;
            float p13 = (c10 + 1 < 301) ? __expf(s1[3]) : 0.f;
            rs0 += (p00 + p01) + (p10 + p11);
            rs1 += (p02 + p03) + (p12 + p13);
            unsigned pa[4];
            pa[0] = packbf(p00, p01);
            pa[1] = packbf(p02, p03);
            pa[2] = packbf(p10, p11);
            pa[3] = packbf(p12, p13);
            unsigned bv0[2], bv1[2];
            int jj = jb0 + lr * 2;
            bv0[0] = *(const unsigned*)&sVt[lq * 312 + jj];
            bv0[1] = *(const unsigned*)&sVt[lq * 312 + jj + 8];
            bv1[0] = *(const unsigned*)&sVt[(lq + 8) * 312 + jj];
            bv1[1] = *(const unsigned*)&sVt[(lq + 8) * 312 + jj + 8];
            mma16816(o0, pa, bv0, o0);
            mma16816(o1, pa, bv1, o1);
        }
        rs0 += __shfl_xor_sync(0xffffffffu, rs0, 1);
        rs0 += __shfl_xor_sync(0xffffffffu, rs0, 2);
        rs1 += __shfl_xor_sync(0xffffffffu, rs1, 1);
        rs1 += __shfl_xor_sync(0xffffffffu, rs1, 2);
        float inv0 = 1.f / rs0, inv1 = 1.f / rs1;
        int row0 = base + lq, row1 = row0 + 8;
        if (row0 < 301) {
            float* op = g_o + (b * 301 + row0) * 64 + h * 16 + lr * 2;
            *(float2*)op       = make_float2(o0[0] * inv0, o0[1] * inv0);
            *(float2*)(op + 8) = make_float2(o1[0] * inv0, o1[1] * inv0);
        }
        if (row1 < 301) {
            float* op = g_o + (b * 301 + row1) * 64 + h * 16 + lr * 2;
            *(float2*)op       = make_float2(o0[2] * inv1, o0[3] * inv1);
            *(float2*)(op + 8) = make_float2(o1[2] * inv1, o1[3] * inv1);
        }
    }
}

// K8: out projection + residual, 128 threads, 4x4 blocking
__global__ void __launch_bounds__(128) k_proj(int l, const float* __restrict__ W,
                                              const float* __restrict__ B) {
    __shared__ float s_w[64 * 66], s_o[32 * 66];
    int b = blockIdx.x, tbase = blockIdx.y * 32, tid = threadIdx.x;
    for (int i = tid; i < 4096; i += 128) {
        int j = i >> 6, k = i & 63;
        s_w[j * 66 + k] = W[l * 4096 + i];
    }
    for (int i = tid; i < 2048; i += 128) {
        int t = i >> 6, k = i & 63, tg = tbase + t;
        s_o[t * 66 + k] = (tg < 301) ? g_o[(b * 301 + tg) * 64 + k] : 0.f;
    }
    __syncthreads();
    int t0 = tid & 7, j0 = (tid >> 3) * 4;
    float2 acc[4][4];
    #pragma unroll
    for (int m = 0; m < 4; m++)
    #pragma unroll
    for (int n = 0; n < 4; n++) acc[m][n] = make_float2(0.f, 0.f);
    const float2* x2 = (const float2*)s_o;
    const float2* w2 = (const float2*)s_w;
    #pragma unroll 4
    for (int k = 0; k < 32; k++) {
        float2 xv[4], wv[4];
        #pragma unroll
        for (int m = 0; m < 4; m++) xv[m] = x2[(t0 + 8 * m) * 33 + k];
        #pragma unroll
        for (int n = 0; n < 4; n++) wv[n] = w2[(j0 + n) * 33 + k];
        #pragma unroll
        for (int m = 0; m < 4; m++)
        #pragma unroll
        for (int n = 0; n < 4; n++) acc[m][n] = ffma2(xv[m], wv[n], acc[m][n]);
    }
    float4 bb = *(const float4*)(B + l * 64 + j0);
    #pragma unroll
    for (int m = 0; m < 4; m++) {
        int tg = tbase + t0 + 8 * m;
        if (tg < 301) {
            float4* xp = (float4*)(g_x + (b * 301 + tg) * 64 + j0);
            float4 v = *xp;
            v.x += acc[m][0].x + acc[m][0].y + bb.x;
            v.y += acc[m][1].x + acc[m][1].y + bb.y;
            v.z += acc[m][2].x + acc[m][2].y + bb.z;
            v.w += acc[m][3].x + acc[m][3].y + bb.w;
            *xp = v;
        }
    }
}

// K9: LN2 + MLP + residual
__global__ void k_ff(int l, const float* __restrict__ lg, const float* __restrict__ lb,
                     const float* __restrict__ w1, const float* __restrict__ b1,
                     const float* __restrict__ w2, const float* __restrict__ b2) {
    __shared__ float s_w1[512], s_w2[512], s_b1[8], s_b2[64], s_g[64], s_bb[64];
    int tid = threadIdx.x;
    for (int i = tid; i < 512; i += 256) { s_w1[i] = w1[l * 512 + i]; s_w2[i] = w2[l * 512 + i]; }
    if (tid < 8)  s_b1[tid] = b1[l * 8 + tid];
    if (tid < 64) { s_b2[tid] = b2[l * 64 + tid]; s_g[tid] = lg[l * 64 + tid]; s_bb[tid] = lb[l * 64 + tid]; }
    __syncthreads();
    int gid = blockIdx.x * 256 + tid;
    float* xr = g_x + gid * 64;
    float xv[64];
    float4* x4 = (float4*)xr;
    #pragma unroll
    for (int i = 0; i < 16; i++) {
        float4 v = x4[i];
        xv[4 * i] = v.x; xv[4 * i + 1] = v.y; xv[4 * i + 2] = v.z; xv[4 * i + 3] = v.w;
    }
    float s = 0.f;
    #pragma unroll
    for (int k = 0; k < 64; k++) s += xv[k];
    float m = s * (1.f / 64.f), sq = 0.f;
    #pragma unroll
    for (int k = 0; k < 64; k++) { float d = xv[k] - m; sq += d * d; }
    float rstd = rsqrtf(sq * (1.f / 64.f) + 1e-5f);
    float hid[8];
    #pragma unroll
    for (int mm = 0; mm < 8; mm++) hid[mm] = s_b1[mm];
    #pragma unroll
    for (int k = 0; k < 64; k++) {
        float xn = (xv[k] - m) * rstd * s_g[k] + s_bb[k];
        #pragma unroll
        for (int mm = 0; mm < 8; mm++) hid[mm] += xn * s_w1[mm * 64 + k];
    }
    #pragma unroll
    for (int mm = 0; mm < 8; mm++) {
        float hv = hid[mm];
        hid[mm] = 0.5f * hv * (1.f + erff(hv * 0.70710678118654752f));
    }
    #pragma unroll
    for (int k = 0; k < 64; k++) {
        float acc = s_b2[k];
        #pragma unroll
        for (int mm = 0; mm < 8; mm++) acc += hid[mm] * s_w2[k * 8 + mm];
        xv[k] += acc;
    }
    #pragma unroll
    for (int i = 0; i < 16; i++)
        x4[i] = make_float4(xv[4 * i], xv[4 * i + 1], xv[4 * i + 2], xv[4 * i + 3]);
}

// K10: head
__global__ void k_head(const float* __restrict__ hg, const float* __restrict__ hb,
                       const float* __restrict__ W, const float* __restrict__ B,
                       float* __restrict__ out) {
    __shared__ float s_z[128], s_red[8];
    int b = blockIdx.x, tid = threadIdx.x;
    int warp = tid >> 5, lane = tid & 31;
    float z = (tid < 64) ? g_x[b * 301 * 64 + tid] : g_y[b * 64 + tid - 64];
    float s = z;
    #pragma unroll
    for (int o = 16; o; o >>= 1) s += __shfl_xor_sync(0xffffffffu, s, o);
    if (lane == 0) s_red[warp] = s;
    __syncthreads();
    float m = (s_red[0] + s_red[1] + s_red[2] + s_red[3]) * (1.f / 128.f);
    float d = z - m, sq = d * d;
    #pragma unroll
    for (int o = 16; o; o >>= 1) sq += __shfl_xor_sync(0xffffffffu, sq, o);
    if (lane == 0) s_red[4 + warp] = sq;
    __syncthreads();
    float var = (s_red[4] + s_red[5] + s_red[6] + s_red[7]) * (1.f / 128.f);
    float rstd = rsqrtf(var + 1e-5f);
    s_z[tid] = d * rstd * hg[tid] + hb[tid];
    __syncthreads();
    if (tid < 16) {
        float acc = B[tid];
        const float* wr = W + tid * 128;
        #pragma unroll 16
        for (int k = 0; k < 128; k++) acc += s_z[k] * wr[k];
        out[b * 16 + tid] = acc;
    }
}

extern "C" void kernel_launch(void* const* d_in, const int* in_sizes, int n_in,
                              void* d_out, int out_size) {
    const float* input   = (const float*)d_in[0];
    const float* sse_w   = (const float*)d_in[1];
    const float* sse_b   = (const float*)d_in[2];
    const float* conv1_w = (const float*)d_in[3];
    const float* conv1_b = (const float*)d_in[4];
    const float* conv2_w = (const float*)d_in[5];
    const float* conv2_b = (const float*)d_in[6];
    const float* dense1_w= (const float*)d_in[7];
    const float* dense1_b= (const float*)d_in[8];
    const float* patch_w = (const float*)d_in[9];
    const float* patch_b = (const float*)d_in[10];
    const float* cls_tok = (const float*)d_in[11];
    const float* pos_emb = (const float*)d_in[12];
    const float* ln1_g   = (const float*)d_in[13];
    const float* ln1_b   = (const float*)d_in[14];
    const float* qkv_w   = (const float*)d_in[15];
    const float* ao_w    = (const float*)d_in[16];
    const float* ao_b    = (const float*)d_in[17];
    const float* ln2_g   = (const float*)d_in[18];
    const float* ln2_b   = (const float*)d_in[19];
    const float* ff1_w   = (const float*)d_in[20];
    const float* ff1_b   = (const float*)d_in[21];
    const float* ff2_w   = (const float*)d_in[22];
    const float* ff2_b   = (const float*)d_in[23];
    const float* hln_g   = (const float*)d_in[24];
    const float* hln_b   = (const float*)d_in[25];
    const float* head_w  = (const float*)d_in[26];
    const float* head_b  = (const float*)d_in[27];
    float* out = (float*)d_out;

    static bool attr_done = false;
    if (!attr_done) {
        cudaFuncSetAttribute(k_conv2, cudaFuncAttributeMaxDynamicSharedMemorySize, 99200);
        attr_done = true;
    }

    k_sse<<<512, 256>>>(input, sse_w, sse_b);                            // #1
    k_patch<<<512, 256>>>(patch_w, patch_b, cls_tok, pos_emb);           // #2
    for (int l = 0; l < 5; l++) {
        k_qkv<<<dim3(512, 5), 512>>>(l, ln1_g, ln1_b, qkv_w);            // #3 (l=0)
        k_attn<<<dim3(512, 4), 320>>>();                                 // #4 (l=0) -> profiled
        k_proj<<<dim3(512, 10), 128>>>(l, ao_w, ao_b);
        k_ff<<<602, 256>>>(l, ln2_g, ln2_b, ff1_w, ff1_b, ff2_w, ff2_b);
    }
    k_conv1<<<512, 256>>>(conv1_w, conv1_b);
    k_conv2<<<dim3(512, 4), 256, 99200>>>(conv2_w, conv2_b);
    k_dense1<<<dim3(32, 16), 256>>>(dense1_w);
    k_yred<<<128, 256>>>(dense1_b);
    k_head<<<512, 128>>>(hln_g, hln_b, head_w, head_b, out);
}

// round 16
// speedup vs baseline: 2.4145x; 1.0896x over previous
#include <cuda_runtime.h>
#include <cuda_bf16.h>
#include <cstring>
#include <math.h>

static __device__ float g_xs[512 * 7500];
static __device__ float g_h1[512 * 42336];
static __device__ float g_h2[512 * 9344];
static __device__ float g_ypart[16 * 512 * 64];
static __device__ float g_y[512 * 64];
static __device__ float g_x[512 * 301 * 64];
static __device__ float g_qkv[512 * 301 * 192];   // token-major [b][301][192]
static __device__ float g_o[512 * 301 * 64];

__device__ __forceinline__ float2 ffma2(float2 a, float2 b, float2 c) {
    unsigned long long ua, ub, uc, ud;
    memcpy(&ua, &a, 8); memcpy(&ub, &b, 8); memcpy(&uc, &c, 8);
    asm("fma.rn.f32x2 %0, %1, %2, %3;" : "=l"(ud) : "l"(ua), "l"(ub), "l"(uc));
    float2 d; memcpy(&d, &ud, 8);
    return d;
}

__device__ __forceinline__ unsigned packbf(float x, float y) {
    __nv_bfloat162 t = __floats2bfloat162_rn(x, y);
    unsigned u; memcpy(&u, &t, 4);
    return u;
}

__device__ __forceinline__ void mma16816(float* d, const unsigned* a,
                                         const unsigned* b, const float* c) {
    asm volatile(
        "mma.sync.aligned.m16n8k16.row.col.f32.bf16.bf16.f32 "
        "{%0,%1,%2,%3}, {%4,%5,%6,%7}, {%8,%9}, {%10,%11,%12,%13};"
        : "=f"(d[0]), "=f"(d[1]), "=f"(d[2]), "=f"(d[3])
        : "r"(a[0]), "r"(a[1]), "r"(a[2]), "r"(a[3]),
          "r"(b[0]), "r"(b[1]),
          "f"(c[0]), "f"(c[1]), "f"(c[2]), "f"(c[3]));
}

// K1: SSE gate
__global__ void k_sse(const float* __restrict__ in, const float* __restrict__ sw,
                      const float* __restrict__ sb) {
    int b = blockIdx.x, tid = threadIdx.x;
    __shared__ float s_w[300], s_g[25];
    const float* x = in + b * 7500;
    for (int i = tid; i < 300; i += 256) s_w[i] = sw[i];
    __syncthreads();
    int warp = tid >> 5, lane = tid & 31;
    for (int p = warp; p < 25; p += 8) {
        float acc = 0.f;
        const float* xp = x + p * 300;
        for (int c = lane; c < 300; c += 32) acc += xp[c] * s_w[c];
        #pragma unroll
        for (int o = 16; o; o >>= 1) acc += __shfl_xor_sync(0xffffffffu, acc, o);
        if (lane == 0) s_g[p] = 1.f / (1.f + expf(-(acc + sb[0])));
    }
    __syncthreads();
    float* xo = g_xs + b * 7500;
    for (int i = tid; i < 7500; i += 256) xo[i] = x[i] * s_g[i / 300];
}

// K2: conv1 (1->16, 3x3x7) + relu
__global__ void k_conv1(const float* __restrict__ W, const float* __restrict__ B) {
    int b = blockIdx.x, tid = threadIdx.x;
    __shared__ float sx[7552], sw[1008], sb[16];
    const float* xs = g_xs + b * 7500;
    for (int i = tid; i < 7552; i += 256) sx[i] = (i < 7500) ? xs[i] : 0.f;
    for (int i = tid; i < 1008; i += 256) sw[i] = W[i];
    if (tid < 16) sb[tid] = B[tid];
    __syncthreads();
    float* out = g_h1 + b * 42336;
    int warp = tid >> 5, lane = tid & 31, w0 = lane * 10;
    for (int row = warp; row < 144; row += 8) {
        int o = row / 9, dh = row % 9, d = dh / 3, hh = dh % 3;
        const float* wp = sw + o * 63;
        float acc[10];
        #pragma unroll
        for (int u = 0; u < 10; u++) acc[u] = sb[o];
        #pragma unroll
        for (int kd = 0; kd < 3; kd++)
        #pragma unroll
        for (int kh = 0; kh < 3; kh++) {
            const float* ip = sx + (d + kd) * 1500 + (hh + kh) * 300 + w0;
            float iv[16];
            #pragma unroll
            for (int u = 0; u < 16; u++) iv[u] = ip[u];
            const float* wq = wp + kd * 21 + kh * 7;
            #pragma unroll
            for (int kw = 0; kw < 7; kw++) {
                float wv = wq[kw];
                #pragma unroll
                for (int u = 0; u < 10; u++) acc[u] += iv[u + kw] * wv;
            }
        }
        #pragma unroll
        for (int u = 0; u < 10; u++)
            if (w0 + u < 294) out[row * 294 + w0 + u] = fmaxf(acc[u], 0.f);
    }
}

// K3: conv2 (16->32, 3x3x3) + relu, W-tiled grid (512, 4)
__global__ void k_conv2(const float* __restrict__ W, const float* __restrict__ B) {
    extern __shared__ float sm[];
    float* s_in = sm;             // 144 * 76 = 10944
    float* s_w  = sm + 10944;     // 32 * 433 = 13856
    int b = blockIdx.x, w0 = blockIdx.y * 73, tid = threadIdx.x;
    const float* hin = g_h1 + b * 42336;
    for (int i = tid; i < 10944; i += 256) {
        int row = i / 76, c = i % 76;
        s_in[i] = (w0 + c < 294) ? hin[row * 294 + w0 + c] : 0.f;
    }
    for (int i = tid; i < 13824; i += 256)
        s_w[(i / 432) * 433 + (i % 432)] = W[i];
    __syncthreads();
    float* out = g_h2 + b * 9344;
    for (int t = tid; t < 608; t += 256) {
        int oc = t & 31, wl = (t >> 5) * 4;
        const float* wp = s_w + oc * 433;
        float a0 = 0.f, a1 = 0.f, a2 = 0.f, a3 = 0.f;
        for (int ic = 0; ic < 16; ic++)
        #pragma unroll
        for (int kd = 0; kd < 3; kd++)
        #pragma unroll
        for (int kh = 0; kh < 3; kh++) {
            const float* ip = s_in + (ic * 9 + kd * 3 + kh) * 76 + wl;
            float i0 = ip[0], i1 = ip[1], i2 = ip[2];
            float i3 = ip[3], i4 = ip[4], i5 = ip[5];
            const float* wq = wp + (ic * 9 + kd * 3 + kh) * 3;
            float v0 = wq[0], v1 = wq[1], v2 = wq[2];
            a0 += i0 * v0 + i1 * v1 + i2 * v2;
            a1 += i1 * v0 + i2 * v1 + i3 * v2;
            a2 += i2 * v0 + i3 * v1 + i4 * v2;
            a3 += i3 * v0 + i4 * v1 + i5 * v2;
        }
        float bb = B[oc];
        float r[4] = {a0, a1, a2, a3};
        #pragma unroll
        for (int u = 0; u < 4; u++)
            if (wl + u < 73) out[oc * 292 + w0 + wl + u] = fmaxf(r[u] + bb, 0.f);
    }
}

// K4: dense1 (9344->64), split-K 16
__global__ void k_dense1(const float* __restrict__ W) {
    __shared__ float sA[16][33], sB[64][33];
    int rb = blockIdx.x * 16, kc = blockIdx.y * 584, tid = threadIdx.x;
    int r = tid & 15, cg = tid >> 4;
    float a0 = 0.f, a1 = 0.f, a2 = 0.f, a3 = 0.f;
    for (int k0 = 0; k0 < 584; k0 += 32) {
        int kw = 584 - k0 < 32 ? 584 - k0 : 32;
        for (int i = tid; i < 512; i += 256) {
            int col = i & 31;
            sA[i >> 5][col] = (col < kw) ? g_h2[(rb + (i >> 5)) * 9344 + kc + k0 + col] : 0.f;
        }
        for (int i = tid; i < 2048; i += 256) {
            int col = i & 31;
            sB[i >> 5][col] = (col < kw) ? W[(i >> 5) * 9344 + kc + k0 + col] : 0.f;
        }
        __syncthreads();
        #pragma unroll
        for (int kk = 0; kk < 32; kk++) {
            float a = sA[r][kk];
            a0 += a * sB[cg * 4 + 0][kk];
            a1 += a * sB[cg * 4 + 1][kk];
            a2 += a * sB[cg * 4 + 2][kk];
            a3 += a * sB[cg * 4 + 3][kk];
        }
        __syncthreads();
    }
    float* yp = g_ypart + blockIdx.y * 32768 + (rb + r) * 64 + cg * 4;
    yp[0] = a0; yp[1] = a1; yp[2] = a2; yp[3] = a3;
}

__global__ void k_yred(const float* __restrict__ bias) {
    int i = blockIdx.x * 256 + threadIdx.x;
    float acc = bias[i & 63];
    #pragma unroll
    for (int s = 0; s < 16; s++) acc += g_ypart[s * 32768 + i];
    g_y[i] = acc;
}

// K5: patch embed + cls + pos
__global__ void k_patch(const float* __restrict__ pw, const float* __restrict__ pb,
                        const float* __restrict__ cls, const float* __restrict__ pos) {
    __shared__ float s_x[7500], s_w[1600];
    int b = blockIdx.x, tid = threadIdx.x;
    const float* xs = g_xs + b * 7500;
    for (int i = tid; i < 7500; i += 256) s_x[i] = xs[i];
    for (int i = tid; i < 1600; i += 256) s_w[i] = pw[i];
    __syncthreads();
    float* xo = g_x + b * 301 * 64;
    if (tid < 64) xo[tid] = cls[tid] + pos[tid];
    for (int idx = tid; idx < 19200; idx += 256) {
        int t = idx >> 6, o = idx & 63;
        const float* xr = s_x + t * 25;
        const float* wr = s_w + o * 25;
        float acc = pb[o] + pos[(t + 1) * 64 + o];
        #pragma unroll
        for (int p = 0; p < 25; p++) acc += xr[p] * wr[p];
        xo[(t + 1) * 64 + o] = acc;
    }
}

// K6: LN1 + QKV (64->192) via mma.sync bf16, 64 tokens/block, grid (512, 5)
__global__ void __launch_bounds__(512) k_qkv(int l, const float* __restrict__ lg,
                      const float* __restrict__ lb, const float* __restrict__ w) {
    __shared__ __nv_bfloat16 s_w[192 * 68];
    __shared__ __nv_bfloat16 s_xn[64 * 68];
    int b = blockIdx.x, tbase = blockIdx.y * 64, tid = threadIdx.x;
    int warp = tid >> 5, lane = tid & 31;
    for (int i = tid; i < 12288; i += 512)
        s_w[(i >> 6) * 68 + (i & 63)] = __float2bfloat16(w[l * 12288 + i]);
    #pragma unroll
    for (int tt = 0; tt < 4; tt++) {
        int t = warp * 4 + tt, tg = tbase + t;
        float2 v = make_float2(0.f, 0.f);
        if (tg < 301) v = *(const float2*)(g_x + (b * 301 + tg) * 64 + lane * 2);
        float s = v.x + v.y;
        #pragma unroll
        for (int o = 16; o; o >>= 1) s += __shfl_xor_sync(0xffffffffu, s, o);
        float m = s * (1.f / 64.f);
        float d0 = v.x - m, d1 = v.y - m;
        float sq = d0 * d0 + d1 * d1;
        #pragma unroll
        for (int o = 16; o; o >>= 1) sq += __shfl_xor_sync(0xffffffffu, sq, o);
        float rstd = rsqrtf(sq * (1.f / 64.f) + 1e-5f);
        float xn0 = d0 * rstd * lg[l * 64 + lane * 2]     + lb[l * 64 + lane * 2];
        float xn1 = d1 * rstd * lg[l * 64 + lane * 2 + 1] + lb[l * 64 + lane * 2 + 1];
        *(unsigned*)&s_xn[t * 68 + lane * 2] = packbf(xn0, xn1);
    }
    __syncthreads();
    int m = warp & 3, nc = warp >> 2;
    int lq = lane >> 2, lr = lane & 3;
    unsigned a[4][4];
    #pragma unroll
    for (int kk = 0; kk < 4; kk++) {
        int kof = kk * 16;
        a[kk][0] = *(const unsigned*)&s_xn[(m * 16 + lq) * 68 + kof + lr * 2];
        a[kk][1] = *(const unsigned*)&s_xn[(m * 16 + 8 + lq) * 68 + kof + lr * 2];
        a[kk][2] = *(const unsigned*)&s_xn[(m * 16 + lq) * 68 + kof + lr * 2 + 8];
        a[kk][3] = *(const unsigned*)&s_xn[(m * 16 + 8 + lq) * 68 + kof + lr * 2 + 8];
    }
    int tg0 = tbase + m * 16 + lq, tg1 = tg0 + 8;
    #pragma unroll
    for (int n8 = 0; n8 < 6; n8++) {
        int col0 = nc * 48 + n8 * 8;
        float dacc[4] = {0.f, 0.f, 0.f, 0.f};
        #pragma unroll
        for (int kk = 0; kk < 4; kk++) {
            unsigned bf[2];
            bf[0] = *(const unsigned*)&s_w[(col0 + lq) * 68 + kk * 16 + lr * 2];
            bf[1] = *(const unsigned*)&s_w[(col0 + lq) * 68 + kk * 16 + lr * 2 + 8];
            mma16816(dacc, a[kk], bf, dacc);
        }
        if (tg0 < 301)
            *(float2*)(g_qkv + (b * 301 + tg0) * 192 + col0 + lr * 2) = make_float2(dacc[0], dacc[1]);
        if (tg1 < 301)
            *(float2*)(g_qkv + (b * 301 + tg1) * 192 + col0 + lr * 2) = make_float2(dacc[2], dacc[3]);
    }
}

// K7: tensor-core flash attention per (b, head), mma.sync m16n8k16 bf16
__global__ void __launch_bounds__(320) k_attn() {
    __shared__ __nv_bfloat16 sQ[304 * 16];
    __shared__ __nv_bfloat16 sK[304 * 16];
    __shared__ __nv_bfloat16 sVt[16 * 312];
    int b = blockIdx.x, h = blockIdx.y, tid = threadIdx.x;
    const float* qkv = g_qkv + b * 301 * 192;
    for (int i = tid; i < 304 * 4; i += 320) {
        int j = i >> 2, dq = (i & 3) * 4;
        float4 qv = make_float4(0.f, 0.f, 0.f, 0.f), kv = qv, vv = qv;
        if (j < 301) {
            const float* base = qkv + j * 192 + h * 16 + dq;
            qv = *(const float4*)(base);
            kv = *(const float4*)(base + 64);
            vv = *(const float4*)(base + 128);
        }
        *(unsigned*)&sQ[j * 16 + dq]     = packbf(qv.x * 0.25f, qv.y * 0.25f);
        *(unsigned*)&sQ[j * 16 + dq + 2] = packbf(qv.z * 0.25f, qv.w * 0.25f);
        *(unsigned*)&sK[j * 16 + dq]     = packbf(kv.x, kv.y);
        *(unsigned*)&sK[j * 16 + dq + 2] = packbf(kv.z, kv.w);
        sVt[(dq + 0) * 312 + j] = __float2bfloat16(vv.x);
        sVt[(dq + 1) * 312 + j] = __float2bfloat16(vv.y);
        sVt[(dq + 2) * 312 + j] = __float2bfloat16(vv.z);
        sVt[(dq + 3) * 312 + j] = __float2bfloat16(vv.w);
    }
    __syncthreads();
    int warp = tid >> 5, l = tid & 31;
    int lq = l >> 2, lr = l & 3;
    for (int qc = warp; qc < 19; qc += 10) {
        int base = qc * 16;
        unsigned a[4];
        a[0] = *(const unsigned*)&sQ[(base + lq) * 16 + lr * 2];
        a[1] = *(const unsigned*)&sQ[(base + 8 + lq) * 16 + lr * 2];
        a[2] = *(const unsigned*)&sQ[(base + lq) * 16 + lr * 2 + 8];
        a[3] = *(const unsigned*)&sQ[(base + 8 + lq) * 16 + lr * 2 + 8];
        float o0[4] = {0.f, 0.f, 0.f, 0.f}, o1[4] = {0.f, 0.f, 0.f, 0.f};
        float rs0 = 0.f, rs1 = 0.f;
        const float zc[4] = {0.f, 0.f, 0.f, 0.f};
        for (int cc = 0; cc < 19; cc++) {
            int jb0 = cc * 16, jb1 = jb0 + 8;
            unsigned bk0[2], bk1[2];
            bk0[0] = *(const unsigned*)&sK[(jb0 + lq) * 16 + lr * 2];
            bk0[1] = *(const unsigned*)&sK[(jb0 + lq) * 16 + lr * 2 + 8];
            bk1[0] = *(const unsigned*)&sK[(jb1 + lq) * 16 + lr * 2];
            bk1[1] = *(const unsigned*)&sK[(jb1 + lq) * 16 + lr * 2 + 8];
            float s0[4], s1[4];
            mma16816(s0, a, bk0, zc);
            mma16816(s1, a, bk1, zc);
            int c00 = jb0 + lr * 2, c10 = jb1 + lr * 2;
            float p00 = (c00 < 301)     ? __expf(s0[0]) : 0.f;
            float p01 = (c00 + 1 < 301) ? __expf(s0[1]) : 0.f;
            float p02 = (c00 < 301)     ? __expf(s0[2]) : 0.f;
            float p03 = (c00 + 1 < 301) ? __expf(s0[3]) : 0.f;
            float p10 = (c10 < 301)     ? __expf(s1[0]) : 0.f;
            float p11 = (c10 + 1 < 301) ? __expf(s1[1]) : 0.f;
            float p12 = (c10 < 301)     ? __expf(s1[2]) : 0.f;
            float p13 = (c10 + 1 < 301) ? __expf(s1[3]) : 0.f;
            rs0 += (p00 + p01) + (p10 + p11);
            rs1 += (p02 + p03) + (p12 + p13);
            unsigned pa[4];
            pa[0] = packbf(p00, p01);
            pa[1] = packbf(p02, p03);
            pa[2] = packbf(p10, p11);
            pa[3] = packbf(p12, p13);
            unsigned bv0[2], bv1[2];
            int jj = jb0 + lr * 2;
            bv0[0] = *(const unsigned*)&sVt[lq * 312 + jj];
            bv0[1] = *(const unsigned*)&sVt[lq * 312 + jj + 8];
            bv1[0] = *(const unsigned*)&sVt[(lq + 8) * 312 + jj];
            bv1[1] = *(const unsigned*)&sVt[(lq + 8) * 312 + jj + 8];
            mma16816(o0, pa, bv0, o0);
            mma16816(o1, pa, bv1, o1);
        }
        rs0 += __shfl_xor_sync(0xffffffffu, rs0, 1);
        rs0 += __shfl_xor_sync(0xffffffffu, rs0, 2);
        rs1 += __shfl_xor_sync(0xffffffffu, rs1, 1);
        rs1 += __shfl_xor_sync(0xffffffffu, rs1, 2);
        float inv0 = 1.f / rs0, inv1 = 1.f / rs1;
        int row0 = base + lq, row1 = row0 + 8;
        if (row0 < 301) {
            float* op = g_o + (b * 301 + row0) * 64 + h * 16 + lr * 2;
            *(float2*)op       = make_float2(o0[0] * inv0, o0[1] * inv0);
            *(float2*)(op + 8) = make_float2(o1[0] * inv0, o1[1] * inv0);
        }
        if (row1 < 301) {
            float* op = g_o + (b * 301 + row1) * 64 + h * 16 + lr * 2;
            *(float2*)op       = make_float2(o0[2] * inv1, o0[3] * inv1);
            *(float2*)(op + 8) = make_float2(o1[2] * inv1, o1[3] * inv1);
        }
    }
}

// K8: out projection + residual via mma.sync bf16, 64 tokens/block, grid (512, 5)
__global__ void __launch_bounds__(512) k_proj(int l, const float* __restrict__ W,
                                              const float* __restrict__ B) {
    __shared__ __nv_bfloat16 s_w[64 * 68];
    __shared__ __nv_bfloat16 s_o[64 * 68];
    int b = blockIdx.x, tbase = blockIdx.y * 64, tid = threadIdx.x;
    for (int i = tid; i < 4096; i += 512)
        s_w[(i >> 6) * 68 + (i & 63)] = __float2bfloat16(W[l * 4096 + i]);
    for (int i = tid; i < 4096; i += 512) {
        int t = i >> 6, k = i & 63, tg = tbase + t;
        s_o[t * 68 + k] = __float2bfloat16((tg < 301) ? g_o[(b * 301 + tg) * 64 + k] : 0.f);
    }
    __syncthreads();
    int warp = tid >> 5, lane = tid & 31;
    int m = warp & 3, nc = warp >> 2;        // 4 m-tiles x 4 col-chunks of 16
    int lq = lane >> 2, lr = lane & 3;
    unsigned a[4][4];
    #pragma unroll
    for (int kk = 0; kk < 4; kk++) {
        int kof = kk * 16;
        a[kk][0] = *(const unsigned*)&s_o[(m * 16 + lq) * 68 + kof + lr * 2];
        a[kk][1] = *(const unsigned*)&s_o[(m * 16 + 8 + lq) * 68 + kof + lr * 2];
        a[kk][2] = *(const unsigned*)&s_o[(m * 16 + lq) * 68 + kof + lr * 2 + 8];
        a[kk][3] = *(const unsigned*)&s_o[(m * 16 + 8 + lq) * 68 + kof + lr * 2 + 8];
    }
    int tg0 = tbase + m * 16 + lq, tg1 = tg0 + 8;
    #pragma unroll
    for (int n8 = 0; n8 < 2; n8++) {
        int col0 = nc * 16 + n8 * 8;
        float dacc[4] = {0.f, 0.f, 0.f, 0.f};
        #pragma unroll
        for (int kk = 0; kk < 4; kk++) {
            unsigned bf[2];
            bf[0] = *(const unsigned*)&s_w[(col0 + lq) * 68 + kk * 16 + lr * 2];
            bf[1] = *(const unsigned*)&s_w[(col0 + lq) * 68 + kk * 16 + lr * 2 + 8];
            mma16816(dacc, a[kk], bf, dacc);
        }
        float2 bb = *(const float2*)(B + l * 64 + col0 + lr * 2);
        if (tg0 < 301) {
            float2* xp = (float2*)(g_x + (b * 301 + tg0) * 64 + col0 + lr * 2);
            float2 v = *xp;
            v.x += dacc[0] + bb.x;
            v.y += dacc[1] + bb.y;
            *xp = v;
        }
        if (tg1 < 301) {
            float2* xp = (float2*)(g_x + (b * 301 + tg1) * 64 + col0 + lr * 2);
            float2 v = *xp;
            v.x += dacc[2] + bb.x;
            v.y += dacc[3] + bb.y;
            *xp = v;
        }
    }
}

// K9: LN2 + MLP + residual
__global__ void k_ff(int l, const float* __restrict__ lg, const float* __restrict__ lb,
                     const float* __restrict__ w1, const float* __restrict__ b1,
                     const float* __restrict__ w2, const float* __restrict__ b2) {
    __shared__ float s_w1[512], s_w2[512], s_b1[8], s_b2[64], s_g[64], s_bb[64];
    int tid = threadIdx.x;
    for (int i = tid; i < 512; i += 256) { s_w1[i] = w1[l * 512 + i]; s_w2[i] = w2[l * 512 + i]; }
    if (tid < 8)  s_b1[tid] = b1[l * 8 + tid];
    if (tid < 64) { s_b2[tid] = b2[l * 64 + tid]; s_g[tid] = lg[l * 64 + tid]; s_bb[tid] = lb[l * 64 + tid]; }
    __syncthreads();
    int gid = blockIdx.x * 256 + tid;
    float* xr = g_x + gid * 64;
    float xv[64];
    float4* x4 = (float4*)xr;
    #pragma unroll
    for (int i = 0; i < 16; i++) {
        float4 v = x4[i];
        xv[4 * i] = v.x; xv[4 * i + 1] = v.y; xv[4 * i + 2] = v.z; xv[4 * i + 3] = v.w;
    }
    float s = 0.f;
    #pragma unroll
    for (int k = 0; k < 64; k++) s += xv[k];
    float m = s * (1.f / 64.f), sq = 0.f;
    #pragma unroll
    for (int k = 0; k < 64; k++) { float d = xv[k] - m; sq += d * d; }
    float rstd = rsqrtf(sq * (1.f / 64.f) + 1e-5f);
    float hid[8];
    #pragma unroll
    for (int mm = 0; mm < 8; mm++) hid[mm] = s_b1[mm];
    #pragma unroll
    for (int k = 0; k < 64; k++) {
        float xn = (xv[k] - m) * rstd * s_g[k] + s_bb[k];
        #pragma unroll
        for (int mm = 0; mm < 8; mm++) hid[mm] += xn * s_w1[mm * 64 + k];
    }
    #pragma unroll
    for (int mm = 0; mm < 8; mm++) {
        float hv = hid[mm];
        hid[mm] = 0.5f * hv * (1.f + erff(hv * 0.70710678118654752f));
    }
    #pragma unroll
    for (int k = 0; k < 64; k++) {
        float acc = s_b2[k];
        #pragma unroll
        for (int mm = 0; mm < 8; mm++) acc += hid[mm] * s_w2[k * 8 + mm];
        xv[k] += acc;
    }
    #pragma unroll
    for (int i = 0; i < 16; i++)
        x4[i] = make_float4(xv[4 * i], xv[4 * i + 1], xv[4 * i + 2], xv[4 * i + 3]);
}

// K10: head
__global__ void k_head(const float* __restrict__ hg, const float* __restrict__ hb,
                       const float* __restrict__ W, const float* __restrict__ B,
                       float* __restrict__ out) {
    __shared__ float s_z[128], s_red[8];
    int b = blockIdx.x, tid = threadIdx.x;
    int warp = tid >> 5, lane = tid & 31;
    float z = (tid < 64) ? g_x[b * 301 * 64 + tid] : g_y[b * 64 + tid - 64];
    float s = z;
    #pragma unroll
    for (int o = 16; o; o >>= 1) s += __shfl_xor_sync(0xffffffffu, s, o);
    if (lane == 0) s_red[warp] = s;
    __syncthreads();
    float m = (s_red[0] + s_red[1] + s_red[2] + s_red[3]) * (1.f / 128.f);
    float d = z - m, sq = d * d;
    #pragma unroll
    for (int o = 16; o; o >>= 1) sq += __shfl_xor_sync(0xffffffffu, sq, o);
    if (lane == 0) s_red[4 + warp] = sq;
    __syncthreads();
    float var = (s_red[4] + s_red[5] + s_red[6] + s_red[7]) * (1.f / 128.f);
    float rstd = rsqrtf(var + 1e-5f);
    s_z[tid] = d * rstd * hg[tid] + hb[tid];
    __syncthreads();
    if (tid < 16) {
        float acc = B[tid];
        const float* wr = W + tid * 128;
        #pragma unroll 16
        for (int k = 0; k < 128; k++) acc += s_z[k] * wr[k];
        out[b * 16 + tid] = acc;
    }
}

extern "C" void kernel_launch(void* const* d_in, const int* in_sizes, int n_in,
                              void* d_out, int out_size) {
    const float* input   = (const float*)d_in[0];
    const float* sse_w   = (const float*)d_in[1];
    const float* sse_b   = (const float*)d_in[2];
    const float* conv1_w = (const float*)d_in[3];
    const float* conv1_b = (const float*)d_in[4];
    const float* conv2_w = (const float*)d_in[5];
    const float* conv2_b = (const float*)d_in[6];
    const float* dense1_w= (const float*)d_in[7];
    const float* dense1_b= (const float*)d_in[8];
    const float* patch_w = (const float*)d_in[9];
    const float* patch_b = (const float*)d_in[10];
    const float* cls_tok = (const float*)d_in[11];
    const float* pos_emb = (const float*)d_in[12];
    const float* ln1_g   = (const float*)d_in[13];
    const float* ln1_b   = (const float*)d_in[14];
    const float* qkv_w   = (const float*)d_in[15];
    const float* ao_w    = (const float*)d_in[16];
    const float* ao_b    = (const float*)d_in[17];
    const float* ln2_g   = (const float*)d_in[18];
    const float* ln2_b   = (const float*)d_in[19];
    const float* ff1_w   = (const float*)d_in[20];
    const float* ff1_b   = (const float*)d_in[21];
    const float* ff2_w   = (const float*)d_in[22];
    const float* ff2_b   = (const float*)d_in[23];
    const float* hln_g   = (const float*)d_in[24];
    const float* hln_b   = (const float*)d_in[25];
    const float* head_w  = (const float*)d_in[26];
    const float* head_b  = (const float*)d_in[27];
    float* out = (float*)d_out;

    static bool attr_done = false;
    if (!attr_done) {
        cudaFuncSetAttribute(k_conv2, cudaFuncAttributeMaxDynamicSharedMemorySize, 99200);
        attr_done = true;
    }

    k_sse<<<512, 256>>>(input, sse_w, sse_b);                            // #1
    k_patch<<<512, 256>>>(patch_w, patch_b, cls_tok, pos_emb);           // #2
    for (int l = 0; l < 5; l++) {
        k_qkv<<<dim3(512, 5), 512>>>(l, ln1_g, ln1_b, qkv_w);            // #3 (l=0)
        k_attn<<<dim3(512, 4), 320>>>();                                 // #4 (l=0) -> profiled
        k_proj<<<dim3(512, 5), 512>>>(l, ao_w, ao_b);
        k_ff<<<602, 256>>>(l, ln2_g, ln2_b, ff1_w, ff1_b, ff2_w, ff2_b);
    }
    k_conv1<<<512, 256>>>(conv1_w, conv1_b);
    k_conv2<<<dim3(512, 4), 256, 99200>>>(conv2_w, conv2_b);
    k_dense1<<<dim3(32, 16), 256>>>(dense1_w);
    k_yred<<<128, 256>>>(dense1_b);
    k_head<<<512, 128>>>(hln_g, hln_b, head_w, head_b, out);
}